// round 14
// baseline (speedup 1.0000x reference)
#include <cuda_runtime.h>
#include <cstdint>

// ---------------- problem constants ----------------
#define BATCH 2
#define C3 256
#define HW 48           // lv3 spatial
#define M48 (HW*HW)     // 2304 patch positions
#define HP 50           // padded 48+2
#define NP 2500         // 50*50
#define NPS 2560        // padded GEMM dim (20 * 128)
#define KTILE 32
#define NKSTEPS 8       // 256 / 32
#define STAGES 3
#define GEMM_SMEM (STAGES * KTILE * 128 * 2 * 4)   // 98304 bytes
#define COLINV 4095
#define JINV (1 << 30)

// group tables: 48 groups per row at every level; 9 planes of (6*S*48)
#define NPL3 (6 * 48 * 48)      // 13824
#define NPL2 (6 * 96 * 48)      // 27648
#define NPL1 (6 * 192 * 48)     // 55296
#define TOFS3 0
#define TOFS2 (9 * NPL3)
#define TOFS1 (TOFS2 + 9 * NPL2)
#define TTOT  (TOFS1 + 9 * NPL1)
#define NTB   (NPL3 + NPL2 + NPL1)

// fused transfer thread counts (16 channels, one group per thread)
#define NTG3 (6 * 16 * 48 * 48)    // 221184
#define NTG2 (6 * 8  * 96 * 48)    // 221184
#define NTG1 (6 * 4  * 192 * 48)   // 221184
#define NTALLG (NTG3 + NTG2 + NTG1)

#define NSSQ (2 * BATCH * NP)
#define NPREP (2 * BATCH * C3 * NPS)

// ---------------- scratch (device globals; no runtime alloc) ----------------
__device__ __align__(16) float g_lrp[BATCH * C3 * NPS];
__device__ __align__(16) float g_rfp[BATCH * C3 * NPS];
__device__ __align__(16) float g_E[(size_t)BATCH * NPS * NPS];
__device__ __align__(16) float g_D[(size_t)BATCH * M48 * M48];
__device__ float g_SS[2 * BATCH * NP];
__device__ unsigned long long g_H64[BATCH * M48];  // packed argmax (monoval<<32 | ~l)
__device__ int   g_src[3 * BATCH * M48];
__device__ int   g_toff[TTOT];     // packed group offsets: -1 = invalid tap
__device__ __align__(16) int g_j1[BATCH * M48];    // smallest j with hs[j]=c (COLINV if none)
__device__ int   g_j2[BATCH * M48];                // 2nd smallest (JINV if none)
__device__ int   g_j3[BATCH * M48];                // 3rd smallest (JINV if none)

// ---------------- fused prep (pad images) + ssq (from originals) + H64 init ----------------
__global__ void prep_ssq_kernel(const float* __restrict__ lr, const float* __restrict__ refsr) {
    int t = blockIdx.x * blockDim.x + threadIdx.x;
    if (t < BATCH * M48) g_H64[t] = 0ull;
    if (t < NPREP) {
        int u = t % NPS; int r = t / NPS;
        int c = r % C3; r /= C3;
        int b = r & 1; int which = r >> 1;
        float val = 0.f;
        if (u < NP) {
            int rr = u / HP, cc = u % HP;
            if (rr >= 1 && rr < 49 && cc >= 1 && cc < 49) {
                const float* src = which ? refsr : lr;
                val = src[((size_t)(b * C3 + c)) * M48 + (rr - 1) * HW + (cc - 1)];
            }
        }
        float* dst = which ? g_rfp : g_lrp;
        dst[((size_t)(b * C3 + c)) * NPS + u] = val;
    }
    if (t < NSSQ) {
        int u = t % NP; int b = (t / NP) & 1; int which = t / (BATCH * NP);
        int rr = u / HP, cc = u % HP;
        float acc = 0.f;
        if (rr >= 1 && rr < 49 && cc >= 1 && cc < 49) {
            const float* src = (which ? refsr : lr) + (size_t)b * C3 * M48 + (rr - 1) * HW + (cc - 1);
#pragma unroll 8
            for (int c = 0; c < C3; c++) { float x = src[(size_t)c * M48]; acc += x * x; }
        }
        g_SS[t] = acc;
    }
}

// ---------------- SGEMM: E = lrp^T * rfp (2560x2560, K=256), FFMA2, KTILE=32 ----------------
__device__ __forceinline__ void issue_tile(float* as, float* bs,
                                           const float* Aptr, const float* Bptr,
                                           int kt, int lk, int lc) {
#pragma unroll
    for (int r = 0; r < 4; r++) {
        uint32_t sa = (uint32_t)__cvta_generic_to_shared(as + (lk + 8 * r) * 128 + lc);
        const float* ga = Aptr + ((size_t)kt * KTILE + 8 * r) * NPS;
        asm volatile("cp.async.ca.shared.global [%0], [%1], 16;\n" :: "r"(sa), "l"(ga));
    }
#pragma unroll
    for (int r = 0; r < 4; r++) {
        uint32_t sb = (uint32_t)__cvta_generic_to_shared(bs + (lk + 8 * r) * 128 + lc);
        const float* gb = Bptr + ((size_t)kt * KTILE + 8 * r) * NPS;
        asm volatile("cp.async.ca.shared.global [%0], [%1], 16;\n" :: "r"(sb), "l"(gb));
    }
    asm volatile("cp.async.commit_group;\n" ::: "memory");
}

__global__ void __launch_bounds__(256) gemm_kernel() {
    int b = blockIdx.z;
    const float* A = g_lrp + (size_t)b * C3 * NPS;
    const float* B = g_rfp + (size_t)b * C3 * NPS;
    float* C = g_E + (size_t)b * NPS * NPS;

    extern __shared__ __align__(16) float smemf[];
    float* smA = smemf;
    float* smB = smemf + STAGES * KTILE * 128;

    int tid = threadIdx.x;
    int iBase = blockIdx.x * 128;
    int jBase = blockIdx.y * 128;
    int lk = tid >> 5;
    int lc = (tid & 31) << 2;
    const float* Aptr = A + (size_t)lk * NPS + iBase + lc;
    const float* Bptr = B + (size_t)lk * NPS + jBase + lc;

    issue_tile(smA + 0 * KTILE * 128, smB + 0 * KTILE * 128, Aptr, Bptr, 0, lk, lc);
    issue_tile(smA + 1 * KTILE * 128, smB + 1 * KTILE * 128, Aptr, Bptr, 1, lk, lc);

    int ty = tid >> 4, tx = tid & 15;

    unsigned long long accp[8][4];
#pragma unroll
    for (int i = 0; i < 8; i++)
#pragma unroll
        for (int j = 0; j < 4; j++) accp[i][j] = 0ull;

    for (int kt = 0; kt < NKSTEPS; kt++) {
        asm volatile("cp.async.wait_group 1;\n" ::: "memory");
        __syncthreads();
        if (kt + 2 < NKSTEPS) {
            int st = (kt + 2) % STAGES;
            issue_tile(smA + st * KTILE * 128, smB + st * KTILE * 128, Aptr, Bptr, kt + 2, lk, lc);
        }
        int cur = kt % STAGES;
        const float* As = smA + cur * KTILE * 128;
        const float* Bs = smB + cur * KTILE * 128;
#pragma unroll
        for (int kk = 0; kk < KTILE; kk++) {
            float4 a0 = *(const float4*)&As[kk * 128 + ty * 4];
            float4 a1 = *(const float4*)&As[kk * 128 + 64 + ty * 4];
            unsigned long long bp[4];
            *(ulonglong2*)(bp)     = *(const ulonglong2*)&Bs[kk * 128 + tx * 4];
            *(ulonglong2*)(bp + 2) = *(const ulonglong2*)&Bs[kk * 128 + 64 + tx * 4];
            float ar[8] = {a0.x, a0.y, a0.z, a0.w, a1.x, a1.y, a1.z, a1.w};
#pragma unroll
            for (int i = 0; i < 8; i++) {
                unsigned long long a2;
                asm("mov.b64 %0, {%1, %1};" : "=l"(a2) : "r"(__float_as_uint(ar[i])));
#pragma unroll
                for (int jp = 0; jp < 4; jp++) {
                    asm("fma.rn.f32x2 %0, %1, %2, %0;"
                        : "+l"(accp[i][jp]) : "l"(a2), "l"(bp[jp]));
                }
            }
        }
    }

#pragma unroll
    for (int half = 0; half < 2; half++) {
#pragma unroll
        for (int ii = 0; ii < 4; ii++) {
            int i = half * 4 + ii;
            int row = iBase + half * 64 + ty * 4 + ii;
            float* crow = C + (size_t)row * NPS + jBase;
            *(ulonglong2*)(crow + tx * 4)      = make_ulonglong2(accp[i][0], accp[i][1]);
            *(ulonglong2*)(crow + 64 + tx * 4) = make_ulonglong2(accp[i][2], accp[i][3]);
        }
    }
}

// ---------------- tiled aggregate (di-fold) + inline norms + packed atomic argmax -------
__global__ void __launch_bounds__(256) agg_tile_kernel() {
    int li = blockIdx.x, mi = blockIdx.y, b = blockIdx.z;
    __shared__ __align__(16) float Ps[50 * 56];
    __shared__ __align__(16) float dt[48 * 48];
    __shared__ float invqs[48], invks[48];

    const float* Eb = g_E + (size_t)b * NPS * NPS;
    int tid = threadIdx.x;

    // phase 0: inline inverse norms for this block's m/l ranges
    if (tid < 48) {
        const float* S = g_SS + (0 * BATCH + b) * NP;
        float s = 0.f;
#pragma unroll
        for (int di = 0; di < 3; di++)
#pragma unroll
            for (int dj = 0; dj < 3; dj++)
                s += S[(mi + di) * HP + tid + dj];
        invqs[tid] = 1.0f / fmaxf(sqrtf(s), 1e-12f);
    } else if (tid >= 64 && tid < 112) {
        int j = tid - 64;
        const float* S = g_SS + (1 * BATCH + b) * NP;
        float s = 0.f;
#pragma unroll
        for (int di = 0; di < 3; di++)
#pragma unroll
            for (int dj = 0; dj < 3; dj++)
                s += S[(li + di) * HP + j + dj];
        invks[j] = 1.0f / fmaxf(sqrtf(s), 1e-12f);
    }

    // phase 1: fold three 50x50 E sub-blocks into P
    for (int idx = tid; idx < 1250; idx += 256) {
        int a = idx / 25, c2 = idx - (idx / 25) * 25;
        const float* e0 = Eb + (size_t)((mi + 0) * HP + a) * NPS + (li + 0) * HP + c2 * 2;
        const float* e1 = Eb + (size_t)((mi + 1) * HP + a) * NPS + (li + 1) * HP + c2 * 2;
        const float* e2 = Eb + (size_t)((mi + 2) * HP + a) * NPS + (li + 2) * HP + c2 * 2;
        float2 v0 = *(const float2*)e0;
        float2 v1 = *(const float2*)e1;
        float2 v2 = *(const float2*)e2;
        float2 p;
        p.x = v0.x + v1.x + v2.x;
        p.y = v0.y + v1.y + v2.y;
        *(float2*)&Ps[a * 56 + c2 * 2] = p;
    }
    __syncthreads();

    // phase 2: 576 groups of 4 outputs (3-tap diagonal of P)
    for (int g = tid; g < 576; g += 256) {
        int mj = g / 12, lj0 = (g - (g / 12) * 12) * 4;
        const float* r0 = &Ps[(mj + 0) * 56 + lj0];
        const float* r1 = &Ps[(mj + 1) * 56 + lj0];
        const float* r2 = &Ps[(mj + 2) * 56 + lj0];
        float4 x0 = *(const float4*)r0;
        float4 x1 = *(const float4*)r1;  float4 y1 = *(const float4*)(r1 + 4);
        float4 x2 = *(const float4*)r2;  float4 y2 = *(const float4*)(r2 + 4);
        float s0 = x0.x + x1.y + x2.z;
        float s1 = x0.y + x1.z + x2.w;
        float s2 = x0.z + x1.w + y2.x;
        float s3 = x0.w + y1.x + y2.y;
        int m = mi * 48 + mj;
        int l0 = li * 48 + lj0;
        float qi = invqs[mj];
        float4 o;
        o.x = s0 * qi * invks[lj0];
        o.y = s1 * qi * invks[lj0 + 1];
        o.z = s2 * qi * invks[lj0 + 2];
        o.w = s3 * qi * invks[lj0 + 3];
        *(float4*)&g_D[((size_t)b * M48 + m) * M48 + l0] = o;
        *(float4*)&dt[mj * 48 + lj0] = o;
    }
    __syncthreads();

    // phase 3: per-mj argmax via warp shuffles, then packed atomicMax
    int w = tid >> 5, lane = tid & 31;
#pragma unroll
    for (int r = 0; r < 6; r++) {
        int mj = w * 6 + r;
        float v = dt[mj * 48 + lane]; int idx = lane;
        if (lane < 16) {
            float v2 = dt[mj * 48 + 32 + lane];
            if (v2 > v) { v = v2; idx = 32 + lane; }   // tie keeps smaller idx
        }
#pragma unroll
        for (int off = 16; off; off >>= 1) {
            float v2 = __shfl_down_sync(0xffffffffu, v, off);
            int i2 = __shfl_down_sync(0xffffffffu, idx, off);
            if (v2 > v || (v2 == v && i2 < idx)) { v = v2; idx = i2; }
        }
        if (lane == 0) {
            int m = mi * 48 + mj;
            int l = li * 48 + idx;
            unsigned int ub = __float_as_uint(v);
            unsigned int mono = (ub & 0x80000000u) ? ~ub : (ub | 0x80000000u);
            unsigned long long key = ((unsigned long long)mono << 32) | (0xFFFFFFFFu - (unsigned)l);
            atomicMax(&g_H64[b * M48 + m], key);
        }
    }
}

// ---------------- column index: for each column c, the 3 smallest j with hs[j]=c --------
__global__ void __launch_bounds__(256) colidx_kernel() {
    int b = blockIdx.y;
    int c = blockIdx.x * 256 + threadIdx.x;
    __shared__ int hsx[M48];
    const unsigned long long* Hb = g_H64 + b * M48;
#pragma unroll
    for (int it = 0; it < 9; it++) {
        int j = threadIdx.x + it * 256;
        hsx[j] = (int)(0xFFFFFFFFu - (unsigned)Hb[j]);
    }
    __syncthreads();
    int j1 = -1, j2 = -1, j3 = -1;
    for (int j = 0; j < M48; j++) {
        if (hsx[j] == c) {
            if (j1 < 0) j1 = j;
            else if (j2 < 0) j2 = j;
            else if (j3 < 0) j3 = j;
        }
    }
    g_j1[b * M48 + c] = (j1 < 0) ? COLINV : j1;
    g_j2[b * M48 + c] = (j2 < 0) ? JINV : j2;
    g_j3[b * M48 + c] = (j3 < 0) ? JINV : j3;
}

// ---------------- top-3 via column factorization (coalesced, no gather) ----------------
__device__ __forceinline__ void ins3(float v, int j,
                                     float& v0, int& i0, float& v1, int& i1, float& v2, int& i2) {
    bool b2 = (v > v2) || (v == v2 && j < i2);
    if (b2) {
        bool b1 = (v > v1) || (v == v1 && j < i1);
        if (b1) {
            bool b0 = (v > v0) || (v == v0 && j < i0);
            if (b0) { v2 = v1; i2 = i1; v1 = v0; i1 = i0; v0 = v; i0 = j; }
            else    { v2 = v1; i2 = i1; v1 = v;  i1 = j; }
        } else      { v2 = v;  i2 = j; }
    }
}

// ins3 with payload (column) — thread-0 final merge only
__device__ __forceinline__ void ins3p(float v, int j, int c,
                                      float& v0, int& i0, int& p0,
                                      float& v1, int& i1, int& p1,
                                      float& v2, int& i2, int& p2) {
    bool b2 = (v > v2) || (v == v2 && j < i2);
    if (b2) {
        bool b1 = (v > v1) || (v == v1 && j < i1);
        if (b1) {
            bool b0 = (v > v0) || (v == v0 && j < i0);
            if (b0) { v2 = v1; i2 = i1; p2 = p1; v1 = v0; i1 = i0; p1 = p0; v0 = v; i0 = j; p0 = c; }
            else    { v2 = v1; i2 = i1; p2 = p1; v1 = v;  i1 = j;  p1 = c; }
        } else      { v2 = v;  i2 = j;  p2 = c; }
    }
}

__global__ void __launch_bounds__(256) topk_kernel(float* __restrict__ outS) {
    int m = blockIdx.x, b = blockIdx.y;
    int tid = threadIdx.x;
    const float4* Drow4 = (const float4*)(g_D + ((size_t)b * M48 + m) * M48);
    const int4* J4 = (const int4*)(g_j1 + b * M48);

    // column stage: top-3 columns by (v desc, (j1<<12|c) asc). Sentinel cols masked.
    float v0 = -1e30f, v1 = -1e30f, v2 = -1e30f;
    int   i0 = 1 << 30, i1 = 1 << 30, i2 = 1 << 30;
#pragma unroll
    for (int it = 0; it < 3; it++) {
        int q = tid + it * 256;
        if (q < 576) {
            float4 v = __ldg(&Drow4[q]);
            int4 jj = __ldg(&J4[q]);
            int c = q * 4;
            float vx;
            vx = (jj.x == COLINV) ? -1e30f : v.x; ins3(vx, (jj.x << 12) | (c + 0), v0, i0, v1, i1, v2, i2);
            vx = (jj.y == COLINV) ? -1e30f : v.y; ins3(vx, (jj.y << 12) | (c + 1), v0, i0, v1, i1, v2, i2);
            vx = (jj.z == COLINV) ? -1e30f : v.z; ins3(vx, (jj.z << 12) | (c + 2), v0, i0, v1, i1, v2, i2);
            vx = (jj.w == COLINV) ? -1e30f : v.w; ins3(vx, (jj.w << 12) | (c + 3), v0, i0, v1, i1, v2, i2);
        }
    }
#pragma unroll
    for (int off = 16; off; off >>= 1) {
        float w0 = __shfl_down_sync(0xffffffffu, v0, off);
        float w1 = __shfl_down_sync(0xffffffffu, v1, off);
        float w2 = __shfl_down_sync(0xffffffffu, v2, off);
        int   a0 = __shfl_down_sync(0xffffffffu, i0, off);
        int   a1 = __shfl_down_sync(0xffffffffu, i1, off);
        int   a2 = __shfl_down_sync(0xffffffffu, i2, off);
        ins3(w0, a0, v0, i0, v1, i1, v2, i2);
        ins3(w1, a1, v0, i0, v1, i1, v2, i2);
        ins3(w2, a2, v0, i0, v1, i1, v2, i2);
    }
    __shared__ float wv[8][3];
    __shared__ int   wi[8][3];
    if ((tid & 31) == 0) {
        int w = tid >> 5;
        wv[w][0] = v0; wv[w][1] = v1; wv[w][2] = v2;
        wi[w][0] = i0; wi[w][1] = i1; wi[w][2] = i2;
    }
    __syncthreads();
    if (tid == 0) {
        float r0 = wv[0][0], r1 = wv[0][1], r2 = wv[0][2];
        int   s0 = wi[0][0], s1 = wi[0][1], s2 = wi[0][2];
#pragma unroll
        for (int w = 1; w < 8; w++) {
            ins3(wv[w][0], wi[w][0], r0, s0, r1, s1, r2, s2);
            ins3(wv[w][1], wi[w][1], r0, s0, r1, s1, r2, s2);
            ins3(wv[w][2], wi[w][2], r0, s0, r1, s1, r2, s2);
        }
        // expand top-3 columns into <=9 entry candidates, select final top-3 by (v desc, j asc)
        float rv[3] = {r0, r1, r2};
        int   ri[3] = {s0, s1, s2};
        float f0 = -1e30f, f1 = -1e30f, f2 = -1e30f;
        int   a0 = 1 << 30, a1 = 1 << 30, a2 = 1 << 30;
        int   p0 = 0, p1 = 0, p2 = 0;
#pragma unroll
        for (int k = 0; k < 3; k++) {
            int idx = ri[k];
            int jA = idx >> 12;
            int c  = idx & 0xFFF;
            if (jA >= COLINV || rv[k] <= -1e30f) continue;   // sentinel column
            float val = rv[k];
            ins3p(val, jA, c, f0, a0, p0, f1, a1, p1, f2, a2, p2);
            int jB = g_j2[b * M48 + c];
            if (jB < JINV) ins3p(val, jB, c, f0, a0, p0, f1, a1, p1, f2, a2, p2);
            int jC = g_j3[b * M48 + c];
            if (jC < JINV) ins3p(val, jC, c, f0, a0, p0, f1, a1, p1, f2, a2, p2);
        }
        outS[(0 * BATCH + b) * M48 + m] = f0;
        outS[(1 * BATCH + b) * M48 + m] = f1;
        outS[(2 * BATCH + b) * M48 + m] = f2;
        g_src[(0 * BATCH + b) * M48 + m] = p0;
        g_src[(1 * BATCH + b) * M48 + m] = p1;
        g_src[(2 * BATCH + b) * M48 + m] = p2;
    }
}

// ---------------- build per-GROUP packed gather tables (9 offsets, -1 = invalid) --------
__device__ __forceinline__ void tbuild_one(int R, int S, int tabOfs, int npl, int p) {
    int xg = p % 48; int rest = p / 48;
    int y = rest % S; int ib = rest / S;
    int x0 = xg * R;
    int b = ib & 1, i = ib >> 1;

    const int* srcTab = g_src + (i * BATCH + b) * M48;
    int yp = y + R, xp = x0 + R;
    int v = yp - 3 * R + 1; int milo = (v <= 0) ? 0 : (v + R - 1) / R;
    int mihi = yp / R; if (mihi > 47) mihi = 47;
    v = xp - 3 * R + 1; int mjlo = (v <= 0) ? 0 : (v + R - 1) / R;
    int mjhi = xp / R; if (mjhi > 47) mjhi = 47;

#pragma unroll
    for (int a = 0; a < 3; a++) {
        int mi = milo + a;
#pragma unroll
        for (int e = 0; e < 3; e++) {
            int mj = mjlo + e;
            int u = a * 3 + e;
            int off = -1;
            if (mi <= mihi && mj <= mjhi) {
                int s = srcTab[mi * HW + mj];
                int smi = s / HW, smj = s % HW;
                int ry = y + (smi - mi) * R;
                int rx = x0 + (smj - mj) * R;
                if (ry >= 0 && ry < S && rx >= 0 && rx < S) off = ry * S + rx;
            }
            g_toff[tabOfs + u * npl + p] = off;
        }
    }
}

__global__ void tbuild_all_kernel() {
    int t = blockIdx.x * blockDim.x + threadIdx.x;
    if (t < NPL3)               tbuild_one(1, 48,  TOFS3, NPL3, t);
    else if (t < NPL3 + NPL2)   tbuild_one(2, 96,  TOFS2, NPL2, t - NPL3);
    else if (t < NTB)           tbuild_one(4, 192, TOFS1, NPL1, t - NPL3 - NPL2);
}

// ---------------- fused transfer: group-vectorized table gather ----------------
template <int G>
__device__ __forceinline__ void transfer_one(const float* __restrict__ ref,
                                             float* __restrict__ out,
                                             int C, int S, int tabOfs, int t) {
    int xg = t % 48; int rest = t / 48;
    int y = rest % S; rest /= S;
    int nCh = C / 16;
    int cc = rest % nCh; int ib = rest / nCh;
    int npl = 6 * S * 48;
    int p = (ib * S + y) * 48 + xg;

    int off[9];
#pragma unroll
    for (int u = 0; u < 9; u++) off[u] = g_toff[tabOfs + u * npl + p];

    int b = ib & 1, i = ib >> 1;
    int ss = S * S;
    const float* refb = ref + ((size_t)(b * C + cc * 16)) * ss;
    float* outb = out + ((size_t)(i * BATCH + b) * C + cc * 16) * ss + y * S + xg * G;
#pragma unroll
    for (int c = 0; c < 16; c++) {
        const float* rc = refb + (size_t)c * ss;
        if (G == 4) {
            float a0 = 0.f, a1 = 0.f, a2 = 0.f, a3 = 0.f;
#pragma unroll
            for (int u = 0; u < 9; u++) {
                int o = off[u];
                if (o >= 0) {
                    float4 vv = __ldg((const float4*)(rc + o));
                    a0 += vv.x; a1 += vv.y; a2 += vv.z; a3 += vv.w;
                }
            }
            float4 o4;
            o4.x = a0 * (1.0f / 9.0f); o4.y = a1 * (1.0f / 9.0f);
            o4.z = a2 * (1.0f / 9.0f); o4.w = a3 * (1.0f / 9.0f);
            *(float4*)(outb + (size_t)c * ss) = o4;
        } else if (G == 2) {
            float a0 = 0.f, a1 = 0.f;
#pragma unroll
            for (int u = 0; u < 9; u++) {
                int o = off[u];
                if (o >= 0) {
                    float2 vv = __ldg((const float2*)(rc + o));
                    a0 += vv.x; a1 += vv.y;
                }
            }
            float2 o2;
            o2.x = a0 * (1.0f / 9.0f); o2.y = a1 * (1.0f / 9.0f);
            *(float2*)(outb + (size_t)c * ss) = o2;
        } else {
            float a0 = 0.f;
#pragma unroll
            for (int u = 0; u < 9; u++) {
                int o = off[u];
                if (o >= 0) a0 += __ldg(rc + o);
            }
            outb[(size_t)c * ss] = a0 * (1.0f / 9.0f);
        }
    }
}

__global__ void transfer_all_kernel(const float* __restrict__ ref3, float* __restrict__ out3,
                                    const float* __restrict__ ref2, float* __restrict__ out2,
                                    const float* __restrict__ ref1, float* __restrict__ out1) {
    int t = blockIdx.x * blockDim.x + threadIdx.x;
    if (t < NTG3)             transfer_one<1>(ref3, out3, 256, 48,  TOFS3, t);
    else if (t < NTG3 + NTG2) transfer_one<2>(ref2, out2, 128, 96,  TOFS2, t - NTG3);
    else                      transfer_one<4>(ref1, out1, 64,  192, TOFS1, t - NTG3 - NTG2);
}

// ---------------- launch ----------------
extern "C" void kernel_launch(void* const* d_in, const int* in_sizes, int n_in,
                              void* d_out, int out_size) {
    const float* lr    = (const float*)d_in[0];
    const float* refsr = (const float*)d_in[1];
    const float* ref1  = (const float*)d_in[2];  // (2,64,192,192)
    const float* ref2  = (const float*)d_in[3];  // (2,128,96,96)
    const float* ref3  = (const float*)d_in[4];  // (2,256,48,48)
    float* out = (float*)d_out;

    float* outS  = out;
    float* outT3 = outS + 3 * BATCH * M48;
    float* outT2 = outT3 + 3 * BATCH * C3 * M48;
    float* outT1 = outT2 + 3 * BATCH * 128 * 96 * 96;

    prep_ssq_kernel<<<(NPREP + 255) / 256, 256>>>(lr, refsr);   // 1

    cudaFuncSetAttribute(gemm_kernel, cudaFuncAttributeMaxDynamicSharedMemorySize, GEMM_SMEM);
    gemm_kernel<<<dim3(20, 20, BATCH), 256, GEMM_SMEM>>>();      // 2

    agg_tile_kernel<<<dim3(48, 48, BATCH), 256>>>();             // 3
    colidx_kernel<<<dim3(9, BATCH), 256>>>();                    // 4 (profiled slot)
    topk_kernel<<<dim3(M48, BATCH), 256>>>(outS);                // 5

    tbuild_all_kernel<<<(NTB + 255) / 256, 256>>>();             // 6
    transfer_all_kernel<<<NTALLG / 256, 256>>>(ref3, outT3, ref2, outT2, ref1, outT1);  // 7
}

// round 15
// speedup vs baseline: 1.1312x; 1.1312x over previous
#include <cuda_runtime.h>
#include <cstdint>

// ---------------- problem constants ----------------
#define BATCH 2
#define C3 256
#define HW 48           // lv3 spatial
#define M48 (HW*HW)     // 2304 patch positions
#define HP 50           // padded 48+2
#define NP 2500         // 50*50
#define NPS 2560        // padded GEMM dim (20 * 128)
#define KTILE 32
#define NKSTEPS 8       // 256 / 32
#define STAGES 3
#define GEMM_SMEM (STAGES * KTILE * 128 * 2 * 4)   // 98304 bytes
#define COLINV 4095
#define JINV (1 << 30)

// group tables: 48 groups per row at every level; 9 planes of (6*S*48)
#define NPL3 (6 * 48 * 48)      // 13824
#define NPL2 (6 * 96 * 48)      // 27648
#define NPL1 (6 * 192 * 48)     // 55296
#define TOFS3 0
#define TOFS2 (9 * NPL3)
#define TOFS1 (TOFS2 + 9 * NPL2)
#define TTOT  (TOFS1 + 9 * NPL1)
#define NTB   (NPL3 + NPL2 + NPL1)

// fused transfer thread counts (16 channels, one group per thread)
#define NTG3 (6 * 16 * 48 * 48)    // 221184
#define NTG2 (6 * 8  * 96 * 48)    // 221184
#define NTG1 (6 * 4  * 192 * 48)   // 221184
#define NTALLG (NTG3 + NTG2 + NTG1)

#define NSSQ (2 * BATCH * NP)
#define NPREP (2 * BATCH * C3 * NPS)

// ---------------- scratch (device globals; no runtime alloc) ----------------
__device__ __align__(16) float g_lrp[BATCH * C3 * NPS];
__device__ __align__(16) float g_rfp[BATCH * C3 * NPS];
__device__ __align__(16) float g_E[(size_t)BATCH * NPS * NPS];
__device__ __align__(16) float g_D[(size_t)BATCH * M48 * M48];
__device__ float g_SS[2 * BATCH * NP];
__device__ unsigned long long g_H64[BATCH * M48];  // packed argmax (monoval<<32 | ~l)
__device__ int   g_src[3 * BATCH * M48];
__device__ int   g_toff[TTOT];     // packed group offsets: -1 = invalid tap
__device__ __align__(16) int g_j1[BATCH * M48];    // smallest j with hs[j]=c (COLINV if none)
__device__ int   g_j2[BATCH * M48];                // 2nd smallest (JINV if none)
__device__ int   g_j3[BATCH * M48];                // 3rd smallest (JINV if none)

// ---------------- fused prep (pad images) + ssq (from originals) + H64 init ----------------
__global__ void prep_ssq_kernel(const float* __restrict__ lr, const float* __restrict__ refsr) {
    int t = blockIdx.x * blockDim.x + threadIdx.x;
    if (t < BATCH * M48) g_H64[t] = 0ull;
    if (t < NPREP) {
        int u = t % NPS; int r = t / NPS;
        int c = r % C3; r /= C3;
        int b = r & 1; int which = r >> 1;
        float val = 0.f;
        if (u < NP) {
            int rr = u / HP, cc = u % HP;
            if (rr >= 1 && rr < 49 && cc >= 1 && cc < 49) {
                const float* src = which ? refsr : lr;
                val = src[((size_t)(b * C3 + c)) * M48 + (rr - 1) * HW + (cc - 1)];
            }
        }
        float* dst = which ? g_rfp : g_lrp;
        dst[((size_t)(b * C3 + c)) * NPS + u] = val;
    }
    if (t < NSSQ) {
        int u = t % NP; int b = (t / NP) & 1; int which = t / (BATCH * NP);
        int rr = u / HP, cc = u % HP;
        float acc = 0.f;
        if (rr >= 1 && rr < 49 && cc >= 1 && cc < 49) {
            const float* src = (which ? refsr : lr) + (size_t)b * C3 * M48 + (rr - 1) * HW + (cc - 1);
#pragma unroll 8
            for (int c = 0; c < C3; c++) { float x = src[(size_t)c * M48]; acc += x * x; }
        }
        g_SS[t] = acc;
    }
}

// ---------------- SGEMM: E = lrp^T * rfp (2560x2560, K=256), FFMA2, KTILE=32 ----------------
__device__ __forceinline__ void issue_tile(float* as, float* bs,
                                           const float* Aptr, const float* Bptr,
                                           int kt, int lk, int lc) {
#pragma unroll
    for (int r = 0; r < 4; r++) {
        uint32_t sa = (uint32_t)__cvta_generic_to_shared(as + (lk + 8 * r) * 128 + lc);
        const float* ga = Aptr + ((size_t)kt * KTILE + 8 * r) * NPS;
        asm volatile("cp.async.ca.shared.global [%0], [%1], 16;\n" :: "r"(sa), "l"(ga));
    }
#pragma unroll
    for (int r = 0; r < 4; r++) {
        uint32_t sb = (uint32_t)__cvta_generic_to_shared(bs + (lk + 8 * r) * 128 + lc);
        const float* gb = Bptr + ((size_t)kt * KTILE + 8 * r) * NPS;
        asm volatile("cp.async.ca.shared.global [%0], [%1], 16;\n" :: "r"(sb), "l"(gb));
    }
    asm volatile("cp.async.commit_group;\n" ::: "memory");
}

__global__ void __launch_bounds__(256) gemm_kernel() {
    int b = blockIdx.z;
    const float* A = g_lrp + (size_t)b * C3 * NPS;
    const float* B = g_rfp + (size_t)b * C3 * NPS;
    float* C = g_E + (size_t)b * NPS * NPS;

    extern __shared__ __align__(16) float smemf[];
    float* smA = smemf;
    float* smB = smemf + STAGES * KTILE * 128;

    int tid = threadIdx.x;
    int iBase = blockIdx.x * 128;
    int jBase = blockIdx.y * 128;
    int lk = tid >> 5;
    int lc = (tid & 31) << 2;
    const float* Aptr = A + (size_t)lk * NPS + iBase + lc;
    const float* Bptr = B + (size_t)lk * NPS + jBase + lc;

    issue_tile(smA + 0 * KTILE * 128, smB + 0 * KTILE * 128, Aptr, Bptr, 0, lk, lc);
    issue_tile(smA + 1 * KTILE * 128, smB + 1 * KTILE * 128, Aptr, Bptr, 1, lk, lc);

    int ty = tid >> 4, tx = tid & 15;

    unsigned long long accp[8][4];
#pragma unroll
    for (int i = 0; i < 8; i++)
#pragma unroll
        for (int j = 0; j < 4; j++) accp[i][j] = 0ull;

    for (int kt = 0; kt < NKSTEPS; kt++) {
        asm volatile("cp.async.wait_group 1;\n" ::: "memory");
        __syncthreads();
        if (kt + 2 < NKSTEPS) {
            int st = (kt + 2) % STAGES;
            issue_tile(smA + st * KTILE * 128, smB + st * KTILE * 128, Aptr, Bptr, kt + 2, lk, lc);
        }
        int cur = kt % STAGES;
        const float* As = smA + cur * KTILE * 128;
        const float* Bs = smB + cur * KTILE * 128;
#pragma unroll
        for (int kk = 0; kk < KTILE; kk++) {
            float4 a0 = *(const float4*)&As[kk * 128 + ty * 4];
            float4 a1 = *(const float4*)&As[kk * 128 + 64 + ty * 4];
            unsigned long long bp[4];
            *(ulonglong2*)(bp)     = *(const ulonglong2*)&Bs[kk * 128 + tx * 4];
            *(ulonglong2*)(bp + 2) = *(const ulonglong2*)&Bs[kk * 128 + 64 + tx * 4];
            float ar[8] = {a0.x, a0.y, a0.z, a0.w, a1.x, a1.y, a1.z, a1.w};
#pragma unroll
            for (int i = 0; i < 8; i++) {
                unsigned long long a2;
                asm("mov.b64 %0, {%1, %1};" : "=l"(a2) : "r"(__float_as_uint(ar[i])));
#pragma unroll
                for (int jp = 0; jp < 4; jp++) {
                    asm("fma.rn.f32x2 %0, %1, %2, %0;"
                        : "+l"(accp[i][jp]) : "l"(a2), "l"(bp[jp]));
                }
            }
        }
    }

#pragma unroll
    for (int half = 0; half < 2; half++) {
#pragma unroll
        for (int ii = 0; ii < 4; ii++) {
            int i = half * 4 + ii;
            int row = iBase + half * 64 + ty * 4 + ii;
            float* crow = C + (size_t)row * NPS + jBase;
            *(ulonglong2*)(crow + tx * 4)      = make_ulonglong2(accp[i][0], accp[i][1]);
            *(ulonglong2*)(crow + 64 + tx * 4) = make_ulonglong2(accp[i][2], accp[i][3]);
        }
    }
}

// ---------------- tiled aggregate (di-fold) + inline norms + packed atomic argmax -------
__global__ void __launch_bounds__(256) agg_tile_kernel() {
    int li = blockIdx.x, mi = blockIdx.y, b = blockIdx.z;
    __shared__ __align__(16) float Ps[50 * 56];
    __shared__ __align__(16) float dt[48 * 48];
    __shared__ float invqs[48], invks[48];

    const float* Eb = g_E + (size_t)b * NPS * NPS;
    int tid = threadIdx.x;

    // phase 0: inline inverse norms for this block's m/l ranges
    if (tid < 48) {
        const float* S = g_SS + (0 * BATCH + b) * NP;
        float s = 0.f;
#pragma unroll
        for (int di = 0; di < 3; di++)
#pragma unroll
            for (int dj = 0; dj < 3; dj++)
                s += S[(mi + di) * HP + tid + dj];
        invqs[tid] = 1.0f / fmaxf(sqrtf(s), 1e-12f);
    } else if (tid >= 64 && tid < 112) {
        int j = tid - 64;
        const float* S = g_SS + (1 * BATCH + b) * NP;
        float s = 0.f;
#pragma unroll
        for (int di = 0; di < 3; di++)
#pragma unroll
            for (int dj = 0; dj < 3; dj++)
                s += S[(li + di) * HP + j + dj];
        invks[j] = 1.0f / fmaxf(sqrtf(s), 1e-12f);
    }

    // phase 1: fold three 50x50 E sub-blocks into P
    for (int idx = tid; idx < 1250; idx += 256) {
        int a = idx / 25, c2 = idx - (idx / 25) * 25;
        const float* e0 = Eb + (size_t)((mi + 0) * HP + a) * NPS + (li + 0) * HP + c2 * 2;
        const float* e1 = Eb + (size_t)((mi + 1) * HP + a) * NPS + (li + 1) * HP + c2 * 2;
        const float* e2 = Eb + (size_t)((mi + 2) * HP + a) * NPS + (li + 2) * HP + c2 * 2;
        float2 v0 = *(const float2*)e0;
        float2 v1 = *(const float2*)e1;
        float2 v2 = *(const float2*)e2;
        float2 p;
        p.x = v0.x + v1.x + v2.x;
        p.y = v0.y + v1.y + v2.y;
        *(float2*)&Ps[a * 56 + c2 * 2] = p;
    }
    __syncthreads();

    // phase 2: 576 groups of 4 outputs (3-tap diagonal of P)
    for (int g = tid; g < 576; g += 256) {
        int mj = g / 12, lj0 = (g - (g / 12) * 12) * 4;
        const float* r0 = &Ps[(mj + 0) * 56 + lj0];
        const float* r1 = &Ps[(mj + 1) * 56 + lj0];
        const float* r2 = &Ps[(mj + 2) * 56 + lj0];
        float4 x0 = *(const float4*)r0;
        float4 x1 = *(const float4*)r1;  float4 y1 = *(const float4*)(r1 + 4);
        float4 x2 = *(const float4*)r2;  float4 y2 = *(const float4*)(r2 + 4);
        float s0 = x0.x + x1.y + x2.z;
        float s1 = x0.y + x1.z + x2.w;
        float s2 = x0.z + x1.w + y2.x;
        float s3 = x0.w + y1.x + y2.y;
        int m = mi * 48 + mj;
        int l0 = li * 48 + lj0;
        float qi = invqs[mj];
        float4 o;
        o.x = s0 * qi * invks[lj0];
        o.y = s1 * qi * invks[lj0 + 1];
        o.z = s2 * qi * invks[lj0 + 2];
        o.w = s3 * qi * invks[lj0 + 3];
        *(float4*)&g_D[((size_t)b * M48 + m) * M48 + l0] = o;
        *(float4*)&dt[mj * 48 + lj0] = o;
    }
    __syncthreads();

    // phase 3: per-mj argmax via warp shuffles, then packed atomicMax
    int w = tid >> 5, lane = tid & 31;
#pragma unroll
    for (int r = 0; r < 6; r++) {
        int mj = w * 6 + r;
        float v = dt[mj * 48 + lane]; int idx = lane;
        if (lane < 16) {
            float v2 = dt[mj * 48 + 32 + lane];
            if (v2 > v) { v = v2; idx = 32 + lane; }   // tie keeps smaller idx
        }
#pragma unroll
        for (int off = 16; off; off >>= 1) {
            float v2 = __shfl_down_sync(0xffffffffu, v, off);
            int i2 = __shfl_down_sync(0xffffffffu, idx, off);
            if (v2 > v || (v2 == v && i2 < idx)) { v = v2; idx = i2; }
        }
        if (lane == 0) {
            int m = mi * 48 + mj;
            int l = li * 48 + idx;
            unsigned int ub = __float_as_uint(v);
            unsigned int mono = (ub & 0x80000000u) ? ~ub : (ub | 0x80000000u);
            unsigned long long key = ((unsigned long long)mono << 32) | (0xFFFFFFFFu - (unsigned)l);
            atomicMax(&g_H64[b * M48 + m], key);
        }
    }
}

// ---------------- colidx: warp-per-column 3-smallest j with hs[j]=c ----------------
// merge two ascending triples -> ascending triple of 3 smallest
__device__ __forceinline__ void merge3(int& a0, int& a1, int& a2, int b0, int b1, int b2) {
    int m0 = min(a0, b0), M0 = max(a0, b0);
    int m1 = min(a1, b1), M1 = max(a1, b1);
    int m2 = min(a2, b2);
    int r1 = min(M0, m1);
    int r2 = min(max(M0, m1), min(M1, m2));
    a0 = m0; a1 = r1; a2 = r2;
}

__global__ void __launch_bounds__(256) colidx_kernel() {
    int b = blockIdx.y;
    int tid = threadIdx.x;
    int w = tid >> 5, lane = tid & 31;
    int c = blockIdx.x * 8 + w;
    __shared__ int hsx[M48];
    const unsigned long long* Hb = g_H64 + b * M48;
#pragma unroll
    for (int it = 0; it < 9; it++) {
        int j = tid + it * 256;
        hsx[j] = (int)(0xFFFFFFFFu - (unsigned)Hb[j]);
    }
    __syncthreads();

    int a0 = JINV, a1 = JINV, a2 = JINV;
    for (int j = lane; j < M48; j += 32) {
        if (hsx[j] == c) {
            if (a0 == JINV) a0 = j;
            else if (a1 == JINV) a1 = j;
            else if (a2 == JINV) a2 = j;
        }
    }
#pragma unroll
    for (int off = 16; off; off >>= 1) {
        int b0 = __shfl_down_sync(0xffffffffu, a0, off);
        int b1 = __shfl_down_sync(0xffffffffu, a1, off);
        int b2 = __shfl_down_sync(0xffffffffu, a2, off);
        merge3(a0, a1, a2, b0, b1, b2);
    }
    if (lane == 0) {
        g_j1[b * M48 + c] = (a0 == JINV) ? COLINV : a0;
        g_j2[b * M48 + c] = a1;
        g_j3[b * M48 + c] = a2;
    }
}

// ---------------- top-3 via column factorization, warp-per-m ----------------
__device__ __forceinline__ void ins3(float v, int j,
                                     float& v0, int& i0, float& v1, int& i1, float& v2, int& i2) {
    bool b2 = (v > v2) || (v == v2 && j < i2);
    if (b2) {
        bool b1 = (v > v1) || (v == v1 && j < i1);
        if (b1) {
            bool b0 = (v > v0) || (v == v0 && j < i0);
            if (b0) { v2 = v1; i2 = i1; v1 = v0; i1 = i0; v0 = v; i0 = j; }
            else    { v2 = v1; i2 = i1; v1 = v;  i1 = j; }
        } else      { v2 = v;  i2 = j; }
    }
}

__device__ __forceinline__ void ins3p(float v, int j, int c,
                                      float& v0, int& i0, int& p0,
                                      float& v1, int& i1, int& p1,
                                      float& v2, int& i2, int& p2) {
    bool b2 = (v > v2) || (v == v2 && j < i2);
    if (b2) {
        bool b1 = (v > v1) || (v == v1 && j < i1);
        if (b1) {
            bool b0 = (v > v0) || (v == v0 && j < i0);
            if (b0) { v2 = v1; i2 = i1; p2 = p1; v1 = v0; i1 = i0; p1 = p0; v0 = v; i0 = j; p0 = c; }
            else    { v2 = v1; i2 = i1; p2 = p1; v1 = v;  i1 = j;  p1 = c; }
        } else      { v2 = v;  i2 = j;  p2 = c; }
    }
}

__global__ void __launch_bounds__(256) topk_kernel(float* __restrict__ outS) {
    int b = blockIdx.y;
    int w = threadIdx.x >> 5, lane = threadIdx.x & 31;
    int m = blockIdx.x * 8 + w;
    const float4* Drow4 = (const float4*)(g_D + ((size_t)b * M48 + m) * M48);
    const int4* J4 = (const int4*)(g_j1 + b * M48);

    float v0 = -1e30f, v1 = -1e30f, v2 = -1e30f;
    int   i0 = 1 << 30, i1 = 1 << 30, i2 = 1 << 30;
#pragma unroll
    for (int it = 0; it < 18; it++) {
        int q = lane + it * 32;
        float4 v = __ldg(&Drow4[q]);
        int4 jj = __ldg(&J4[q]);
        int c = q * 4;
        float vx;
        vx = (jj.x == COLINV) ? -1e30f : v.x; ins3(vx, (jj.x << 12) | (c + 0), v0, i0, v1, i1, v2, i2);
        vx = (jj.y == COLINV) ? -1e30f : v.y; ins3(vx, (jj.y << 12) | (c + 1), v0, i0, v1, i1, v2, i2);
        vx = (jj.z == COLINV) ? -1e30f : v.z; ins3(vx, (jj.z << 12) | (c + 2), v0, i0, v1, i1, v2, i2);
        vx = (jj.w == COLINV) ? -1e30f : v.w; ins3(vx, (jj.w << 12) | (c + 3), v0, i0, v1, i1, v2, i2);
    }
#pragma unroll
    for (int off = 16; off; off >>= 1) {
        float w0 = __shfl_down_sync(0xffffffffu, v0, off);
        float w1 = __shfl_down_sync(0xffffffffu, v1, off);
        float w2 = __shfl_down_sync(0xffffffffu, v2, off);
        int   a0 = __shfl_down_sync(0xffffffffu, i0, off);
        int   a1 = __shfl_down_sync(0xffffffffu, i1, off);
        int   a2 = __shfl_down_sync(0xffffffffu, i2, off);
        ins3(w0, a0, v0, i0, v1, i1, v2, i2);
        ins3(w1, a1, v0, i0, v1, i1, v2, i2);
        ins3(w2, a2, v0, i0, v1, i1, v2, i2);
    }
    if (lane == 0) {
        // expand top-3 columns into <=9 entry candidates, select final top-3 by (v desc, j asc)
        float rv[3] = {v0, v1, v2};
        int   ri[3] = {i0, i1, i2};
        float f0 = -1e30f, f1 = -1e30f, f2 = -1e30f;
        int   a0 = 1 << 30, a1 = 1 << 30, a2 = 1 << 30;
        int   p0 = 0, p1 = 0, p2 = 0;
#pragma unroll
        for (int k = 0; k < 3; k++) {
            int idx = ri[k];
            int jA = idx >> 12;
            int c  = idx & 0xFFF;
            if (jA >= COLINV || rv[k] <= -1e30f) continue;
            float val = rv[k];
            ins3p(val, jA, c, f0, a0, p0, f1, a1, p1, f2, a2, p2);
            int jB = g_j2[b * M48 + c];
            if (jB < JINV) ins3p(val, jB, c, f0, a0, p0, f1, a1, p1, f2, a2, p2);
            int jC = g_j3[b * M48 + c];
            if (jC < JINV) ins3p(val, jC, c, f0, a0, p0, f1, a1, p1, f2, a2, p2);
        }
        outS[(0 * BATCH + b) * M48 + m] = f0;
        outS[(1 * BATCH + b) * M48 + m] = f1;
        outS[(2 * BATCH + b) * M48 + m] = f2;
        g_src[(0 * BATCH + b) * M48 + m] = p0;
        g_src[(1 * BATCH + b) * M48 + m] = p1;
        g_src[(2 * BATCH + b) * M48 + m] = p2;
    }
}

// ---------------- build per-GROUP packed gather tables (9 offsets, -1 = invalid) --------
__device__ __forceinline__ void tbuild_one(int R, int S, int tabOfs, int npl, int p) {
    int xg = p % 48; int rest = p / 48;
    int y = rest % S; int ib = rest / S;
    int x0 = xg * R;
    int b = ib & 1, i = ib >> 1;

    const int* srcTab = g_src + (i * BATCH + b) * M48;
    int yp = y + R, xp = x0 + R;
    int v = yp - 3 * R + 1; int milo = (v <= 0) ? 0 : (v + R - 1) / R;
    int mihi = yp / R; if (mihi > 47) mihi = 47;
    v = xp - 3 * R + 1; int mjlo = (v <= 0) ? 0 : (v + R - 1) / R;
    int mjhi = xp / R; if (mjhi > 47) mjhi = 47;

#pragma unroll
    for (int a = 0; a < 3; a++) {
        int mi = milo + a;
#pragma unroll
        for (int e = 0; e < 3; e++) {
            int mj = mjlo + e;
            int u = a * 3 + e;
            int off = -1;
            if (mi <= mihi && mj <= mjhi) {
                int s = srcTab[mi * HW + mj];
                int smi = s / HW, smj = s % HW;
                int ry = y + (smi - mi) * R;
                int rx = x0 + (smj - mj) * R;
                if (ry >= 0 && ry < S && rx >= 0 && rx < S) off = ry * S + rx;
            }
            g_toff[tabOfs + u * npl + p] = off;
        }
    }
}

__global__ void tbuild_all_kernel() {
    int t = blockIdx.x * blockDim.x + threadIdx.x;
    if (t < NPL3)               tbuild_one(1, 48,  TOFS3, NPL3, t);
    else if (t < NPL3 + NPL2)   tbuild_one(2, 96,  TOFS2, NPL2, t - NPL3);
    else if (t < NTB)           tbuild_one(4, 192, TOFS1, NPL1, t - NPL3 - NPL2);
}

// ---------------- fused transfer: group-vectorized table gather ----------------
template <int G>
__device__ __forceinline__ void transfer_one(const float* __restrict__ ref,
                                             float* __restrict__ out,
                                             int C, int S, int tabOfs, int t) {
    int xg = t % 48; int rest = t / 48;
    int y = rest % S; rest /= S;
    int nCh = C / 16;
    int cc = rest % nCh; int ib = rest / nCh;
    int npl = 6 * S * 48;
    int p = (ib * S + y) * 48 + xg;

    int off[9];
#pragma unroll
    for (int u = 0; u < 9; u++) off[u] = g_toff[tabOfs + u * npl + p];

    int b = ib & 1, i = ib >> 1;
    int ss = S * S;
    const float* refb = ref + ((size_t)(b * C + cc * 16)) * ss;
    float* outb = out + ((size_t)(i * BATCH + b) * C + cc * 16) * ss + y * S + xg * G;
#pragma unroll
    for (int c = 0; c < 16; c++) {
        const float* rc = refb + (size_t)c * ss;
        if (G == 4) {
            float a0 = 0.f, a1 = 0.f, a2 = 0.f, a3 = 0.f;
#pragma unroll
            for (int u = 0; u < 9; u++) {
                int o = off[u];
                if (o >= 0) {
                    float4 vv = __ldg((const float4*)(rc + o));
                    a0 += vv.x; a1 += vv.y; a2 += vv.z; a3 += vv.w;
                }
            }
            float4 o4;
            o4.x = a0 * (1.0f / 9.0f); o4.y = a1 * (1.0f / 9.0f);
            o4.z = a2 * (1.0f / 9.0f); o4.w = a3 * (1.0f / 9.0f);
            *(float4*)(outb + (size_t)c * ss) = o4;
        } else if (G == 2) {
            float a0 = 0.f, a1 = 0.f;
#pragma unroll
            for (int u = 0; u < 9; u++) {
                int o = off[u];
                if (o >= 0) {
                    float2 vv = __ldg((const float2*)(rc + o));
                    a0 += vv.x; a1 += vv.y;
                }
            }
            float2 o2;
            o2.x = a0 * (1.0f / 9.0f); o2.y = a1 * (1.0f / 9.0f);
            *(float2*)(outb + (size_t)c * ss) = o2;
        } else {
            float a0 = 0.f;
#pragma unroll
            for (int u = 0; u < 9; u++) {
                int o = off[u];
                if (o >= 0) a0 += __ldg(rc + o);
            }
            outb[(size_t)c * ss] = a0 * (1.0f / 9.0f);
        }
    }
}

__global__ void transfer_all_kernel(const float* __restrict__ ref3, float* __restrict__ out3,
                                    const float* __restrict__ ref2, float* __restrict__ out2,
                                    const float* __restrict__ ref1, float* __restrict__ out1) {
    int t = blockIdx.x * blockDim.x + threadIdx.x;
    if (t < NTG3)             transfer_one<1>(ref3, out3, 256, 48,  TOFS3, t);
    else if (t < NTG3 + NTG2) transfer_one<2>(ref2, out2, 128, 96,  TOFS2, t - NTG3);
    else                      transfer_one<4>(ref1, out1, 64,  192, TOFS1, t - NTG3 - NTG2);
}

// ---------------- launch ----------------
extern "C" void kernel_launch(void* const* d_in, const int* in_sizes, int n_in,
                              void* d_out, int out_size) {
    const float* lr    = (const float*)d_in[0];
    const float* refsr = (const float*)d_in[1];
    const float* ref1  = (const float*)d_in[2];  // (2,64,192,192)
    const float* ref2  = (const float*)d_in[3];  // (2,128,96,96)
    const float* ref3  = (const float*)d_in[4];  // (2,256,48,48)
    float* out = (float*)d_out;

    float* outS  = out;
    float* outT3 = outS + 3 * BATCH * M48;
    float* outT2 = outT3 + 3 * BATCH * C3 * M48;
    float* outT1 = outT2 + 3 * BATCH * 128 * 96 * 96;

    prep_ssq_kernel<<<(NPREP + 255) / 256, 256>>>(lr, refsr);   // 1

    cudaFuncSetAttribute(gemm_kernel, cudaFuncAttributeMaxDynamicSharedMemorySize, GEMM_SMEM);
    gemm_kernel<<<dim3(20, 20, BATCH), 256, GEMM_SMEM>>>();      // 2

    agg_tile_kernel<<<dim3(48, 48, BATCH), 256>>>();             // 3
    colidx_kernel<<<dim3(M48 / 8, BATCH), 256>>>();              // 4 (profiled slot)
    topk_kernel<<<dim3(M48 / 8, BATCH), 256>>>(outS);            // 5

    tbuild_all_kernel<<<(NTB + 255) / 256, 256>>>();             // 6
    transfer_all_kernel<<<NTALLG / 256, 256>>>(ref3, outT3, ref2, outT2, ref1, outT1);  // 7
}

// round 16
// speedup vs baseline: 1.1630x; 1.0280x over previous
#include <cuda_runtime.h>
#include <cstdint>

// ---------------- problem constants ----------------
#define BATCH 2
#define C3 256
#define HW 48
#define M48 (HW*HW)     // 2304
#define HP 50
#define NP 2500
#define NPS 2560
#define KTILE 32
#define NKSTEPS 8
#define STAGES 3
#define GEMM_SMEM (STAGES * KTILE * 128 * 2 * 4)
#define COLINV 4095
#define JINV (1 << 30)

#define NPL3 (6 * 48 * 48)
#define NPL2 (6 * 96 * 48)
#define NPL1 (6 * 192 * 48)
#define TOFS3 0
#define TOFS2 (9 * NPL3)
#define TOFS1 (TOFS2 + 9 * NPL2)
#define TTOT  (TOFS1 + 9 * NPL1)
#define NTB   (NPL3 + NPL2 + NPL1)

#define NTG2 (6 * 8  * 96 * 48)    // 221184
#define NTG1 (6 * 4  * 192 * 48)   // 221184

#define NSSQ (2 * BATCH * NP)
#define NPREP (2 * BATCH * C3 * NPS)

// ---------------- scratch ----------------
__device__ __align__(16) float g_lrp[BATCH * C3 * NPS];
__device__ __align__(16) float g_rfp[BATCH * C3 * NPS];
__device__ __align__(16) float g_E[(size_t)BATCH * NPS * NPS];
__device__ __align__(16) float g_D[(size_t)BATCH * M48 * M48];
__device__ float g_SS[2 * BATCH * NP];
__device__ unsigned long long g_H64[BATCH * M48];
__device__ int   g_src[3 * BATCH * M48];
__device__ int   g_toff[TTOT];
__device__ __align__(16) int g_j1[BATCH * M48];
__device__ int   g_j2[BATCH * M48];
__device__ int   g_j3[BATCH * M48];
__device__ __align__(16) float g_r3T[BATCH * M48 * C3];      // ref3 channel-last  (4.7 MB)
__device__ __align__(16) float g_o3T[6 * M48 * C3];          // lv3 out channel-last (14.2 MB)

// ---------------- fused prep + ssq + H64 init ----------------
__global__ void prep_ssq_kernel(const float* __restrict__ lr, const float* __restrict__ refsr) {
    int t = blockIdx.x * blockDim.x + threadIdx.x;
    if (t < BATCH * M48) g_H64[t] = 0ull;
    if (t < NPREP) {
        int u = t % NPS; int r = t / NPS;
        int c = r % C3; r /= C3;
        int b = r & 1; int which = r >> 1;
        float val = 0.f;
        if (u < NP) {
            int rr = u / HP, cc = u % HP;
            if (rr >= 1 && rr < 49 && cc >= 1 && cc < 49) {
                const float* src = which ? refsr : lr;
                val = src[((size_t)(b * C3 + c)) * M48 + (rr - 1) * HW + (cc - 1)];
            }
        }
        float* dst = which ? g_rfp : g_lrp;
        dst[((size_t)(b * C3 + c)) * NPS + u] = val;
    }
    if (t < NSSQ) {
        int u = t % NP; int b = (t / NP) & 1; int which = t / (BATCH * NP);
        int rr = u / HP, cc = u % HP;
        float acc = 0.f;
        if (rr >= 1 && rr < 49 && cc >= 1 && cc < 49) {
            const float* src = (which ? refsr : lr) + (size_t)b * C3 * M48 + (rr - 1) * HW + (cc - 1);
#pragma unroll 8
            for (int c = 0; c < C3; c++) { float x = src[(size_t)c * M48]; acc += x * x; }
        }
        g_SS[t] = acc;
    }
}

// ---------------- transpose ref3 -> channel-last ----------------
__global__ void t_in3_kernel(const float* __restrict__ ref3) {
    __shared__ float tile[32][33];
    int x0 = blockIdx.x * 32, c0 = blockIdx.y * 32, b = blockIdx.z;
    int tx = threadIdx.x, ty = threadIdx.y;   // 32 x 8
#pragma unroll
    for (int r = 0; r < 32; r += 8)
        tile[ty + r][tx] = ref3[((size_t)(b * C3 + c0 + ty + r)) * M48 + x0 + tx];
    __syncthreads();
#pragma unroll
    for (int r = 0; r < 32; r += 8)
        g_r3T[((size_t)b * M48 + x0 + ty + r) * C3 + c0 + tx] = tile[tx][ty + r];
}

// ---------------- SGEMM (FFMA2, cp.async, KTILE=32) ----------------
__device__ __forceinline__ void issue_tile(float* as, float* bs,
                                           const float* Aptr, const float* Bptr,
                                           int kt, int lk, int lc) {
#pragma unroll
    for (int r = 0; r < 4; r++) {
        uint32_t sa = (uint32_t)__cvta_generic_to_shared(as + (lk + 8 * r) * 128 + lc);
        const float* ga = Aptr + ((size_t)kt * KTILE + 8 * r) * NPS;
        asm volatile("cp.async.ca.shared.global [%0], [%1], 16;\n" :: "r"(sa), "l"(ga));
    }
#pragma unroll
    for (int r = 0; r < 4; r++) {
        uint32_t sb = (uint32_t)__cvta_generic_to_shared(bs + (lk + 8 * r) * 128 + lc);
        const float* gb = Bptr + ((size_t)kt * KTILE + 8 * r) * NPS;
        asm volatile("cp.async.ca.shared.global [%0], [%1], 16;\n" :: "r"(sb), "l"(gb));
    }
    asm volatile("cp.async.commit_group;\n" ::: "memory");
}

__global__ void __launch_bounds__(256) gemm_kernel() {
    int b = blockIdx.z;
    const float* A = g_lrp + (size_t)b * C3 * NPS;
    const float* B = g_rfp + (size_t)b * C3 * NPS;
    float* C = g_E + (size_t)b * NPS * NPS;

    extern __shared__ __align__(16) float smemf[];
    float* smA = smemf;
    float* smB = smemf + STAGES * KTILE * 128;

    int tid = threadIdx.x;
    int iBase = blockIdx.x * 128;
    int jBase = blockIdx.y * 128;
    int lk = tid >> 5;
    int lc = (tid & 31) << 2;
    const float* Aptr = A + (size_t)lk * NPS + iBase + lc;
    const float* Bptr = B + (size_t)lk * NPS + jBase + lc;

    issue_tile(smA + 0 * KTILE * 128, smB + 0 * KTILE * 128, Aptr, Bptr, 0, lk, lc);
    issue_tile(smA + 1 * KTILE * 128, smB + 1 * KTILE * 128, Aptr, Bptr, 1, lk, lc);

    int ty = tid >> 4, tx = tid & 15;

    unsigned long long accp[8][4];
#pragma unroll
    for (int i = 0; i < 8; i++)
#pragma unroll
        for (int j = 0; j < 4; j++) accp[i][j] = 0ull;

    for (int kt = 0; kt < NKSTEPS; kt++) {
        asm volatile("cp.async.wait_group 1;\n" ::: "memory");
        __syncthreads();
        if (kt + 2 < NKSTEPS) {
            int st = (kt + 2) % STAGES;
            issue_tile(smA + st * KTILE * 128, smB + st * KTILE * 128, Aptr, Bptr, kt + 2, lk, lc);
        }
        int cur = kt % STAGES;
        const float* As = smA + cur * KTILE * 128;
        const float* Bs = smB + cur * KTILE * 128;
#pragma unroll
        for (int kk = 0; kk < KTILE; kk++) {
            float4 a0 = *(const float4*)&As[kk * 128 + ty * 4];
            float4 a1 = *(const float4*)&As[kk * 128 + 64 + ty * 4];
            unsigned long long bp[4];
            *(ulonglong2*)(bp)     = *(const ulonglong2*)&Bs[kk * 128 + tx * 4];
            *(ulonglong2*)(bp + 2) = *(const ulonglong2*)&Bs[kk * 128 + 64 + tx * 4];
            float ar[8] = {a0.x, a0.y, a0.z, a0.w, a1.x, a1.y, a1.z, a1.w};
#pragma unroll
            for (int i = 0; i < 8; i++) {
                unsigned long long a2;
                asm("mov.b64 %0, {%1, %1};" : "=l"(a2) : "r"(__float_as_uint(ar[i])));
#pragma unroll
                for (int jp = 0; jp < 4; jp++) {
                    asm("fma.rn.f32x2 %0, %1, %2, %0;"
                        : "+l"(accp[i][jp]) : "l"(a2), "l"(bp[jp]));
                }
            }
        }
    }

#pragma unroll
    for (int half = 0; half < 2; half++) {
#pragma unroll
        for (int ii = 0; ii < 4; ii++) {
            int i = half * 4 + ii;
            int row = iBase + half * 64 + ty * 4 + ii;
            float* crow = C + (size_t)row * NPS + jBase;
            *(ulonglong2*)(crow + tx * 4)      = make_ulonglong2(accp[i][0], accp[i][1]);
            *(ulonglong2*)(crow + 64 + tx * 4) = make_ulonglong2(accp[i][2], accp[i][3]);
        }
    }
}

// ---------------- tiled aggregate (di-fold) + inline norms + packed atomic argmax -------
__global__ void __launch_bounds__(256) agg_tile_kernel() {
    int li = blockIdx.x, mi = blockIdx.y, b = blockIdx.z;
    __shared__ __align__(16) float Ps[50 * 56];
    __shared__ __align__(16) float dt[48 * 48];
    __shared__ float invqs[48], invks[48];

    const float* Eb = g_E + (size_t)b * NPS * NPS;
    int tid = threadIdx.x;

    if (tid < 48) {
        const float* S = g_SS + (0 * BATCH + b) * NP;
        float s = 0.f;
#pragma unroll
        for (int di = 0; di < 3; di++)
#pragma unroll
            for (int dj = 0; dj < 3; dj++)
                s += S[(mi + di) * HP + tid + dj];
        invqs[tid] = 1.0f / fmaxf(sqrtf(s), 1e-12f);
    } else if (tid >= 64 && tid < 112) {
        int j = tid - 64;
        const float* S = g_SS + (1 * BATCH + b) * NP;
        float s = 0.f;
#pragma unroll
        for (int di = 0; di < 3; di++)
#pragma unroll
            for (int dj = 0; dj < 3; dj++)
                s += S[(li + di) * HP + j + dj];
        invks[j] = 1.0f / fmaxf(sqrtf(s), 1e-12f);
    }

    for (int idx = tid; idx < 1250; idx += 256) {
        int a = idx / 25, c2 = idx - (idx / 25) * 25;
        const float* e0 = Eb + (size_t)((mi + 0) * HP + a) * NPS + (li + 0) * HP + c2 * 2;
        const float* e1 = Eb + (size_t)((mi + 1) * HP + a) * NPS + (li + 1) * HP + c2 * 2;
        const float* e2 = Eb + (size_t)((mi + 2) * HP + a) * NPS + (li + 2) * HP + c2 * 2;
        float2 v0 = *(const float2*)e0;
        float2 v1 = *(const float2*)e1;
        float2 v2 = *(const float2*)e2;
        float2 p;
        p.x = v0.x + v1.x + v2.x;
        p.y = v0.y + v1.y + v2.y;
        *(float2*)&Ps[a * 56 + c2 * 2] = p;
    }
    __syncthreads();

    for (int g = tid; g < 576; g += 256) {
        int mj = g / 12, lj0 = (g - (g / 12) * 12) * 4;
        const float* r0 = &Ps[(mj + 0) * 56 + lj0];
        const float* r1 = &Ps[(mj + 1) * 56 + lj0];
        const float* r2 = &Ps[(mj + 2) * 56 + lj0];
        float4 x0 = *(const float4*)r0;
        float4 x1 = *(const float4*)r1;  float4 y1 = *(const float4*)(r1 + 4);
        float4 x2 = *(const float4*)r2;  float4 y2 = *(const float4*)(r2 + 4);
        float s0 = x0.x + x1.y + x2.z;
        float s1 = x0.y + x1.z + x2.w;
        float s2 = x0.z + x1.w + y2.x;
        float s3 = x0.w + y1.x + y2.y;
        int m = mi * 48 + mj;
        int l0 = li * 48 + lj0;
        float qi = invqs[mj];
        float4 o;
        o.x = s0 * qi * invks[lj0];
        o.y = s1 * qi * invks[lj0 + 1];
        o.z = s2 * qi * invks[lj0 + 2];
        o.w = s3 * qi * invks[lj0 + 3];
        *(float4*)&g_D[((size_t)b * M48 + m) * M48 + l0] = o;
        *(float4*)&dt[mj * 48 + lj0] = o;
    }
    __syncthreads();

    int w = tid >> 5, lane = tid & 31;
#pragma unroll
    for (int r = 0; r < 6; r++) {
        int mj = w * 6 + r;
        float v = dt[mj * 48 + lane]; int idx = lane;
        if (lane < 16) {
            float v2 = dt[mj * 48 + 32 + lane];
            if (v2 > v) { v = v2; idx = 32 + lane; }
        }
#pragma unroll
        for (int off = 16; off; off >>= 1) {
            float v2 = __shfl_down_sync(0xffffffffu, v, off);
            int i2 = __shfl_down_sync(0xffffffffu, idx, off);
            if (v2 > v || (v2 == v && i2 < idx)) { v = v2; idx = i2; }
        }
        if (lane == 0) {
            int m = mi * 48 + mj;
            int l = li * 48 + idx;
            unsigned int ub = __float_as_uint(v);
            unsigned int mono = (ub & 0x80000000u) ? ~ub : (ub | 0x80000000u);
            unsigned long long key = ((unsigned long long)mono << 32) | (0xFFFFFFFFu - (unsigned)l);
            atomicMax(&g_H64[b * M48 + m], key);
        }
    }
}

// ---------------- colidx: warp-per-column 3-smallest j with hs[j]=c ----------------
__device__ __forceinline__ void merge3(int& a0, int& a1, int& a2, int b0, int b1, int b2) {
    int m0 = min(a0, b0), M0 = max(a0, b0);
    int m1 = min(a1, b1), M1 = max(a1, b1);
    int m2 = min(a2, b2);
    int r1 = min(M0, m1);
    int r2 = min(max(M0, m1), min(M1, m2));
    a0 = m0; a1 = r1; a2 = r2;
}

__global__ void __launch_bounds__(256) colidx_kernel() {
    int b = blockIdx.y;
    int tid = threadIdx.x;
    int w = tid >> 5, lane = tid & 31;
    int c = blockIdx.x * 8 + w;
    __shared__ int hsx[M48];
    const unsigned long long* Hb = g_H64 + b * M48;
#pragma unroll
    for (int it = 0; it < 9; it++) {
        int j = tid + it * 256;
        hsx[j] = (int)(0xFFFFFFFFu - (unsigned)Hb[j]);
    }
    __syncthreads();

    int a0 = JINV, a1 = JINV, a2 = JINV;
    for (int j = lane; j < M48; j += 32) {
        if (hsx[j] == c) {
            if (a0 == JINV) a0 = j;
            else if (a1 == JINV) a1 = j;
            else if (a2 == JINV) a2 = j;
        }
    }
#pragma unroll
    for (int off = 16; off; off >>= 1) {
        int b0 = __shfl_down_sync(0xffffffffu, a0, off);
        int b1 = __shfl_down_sync(0xffffffffu, a1, off);
        int b2 = __shfl_down_sync(0xffffffffu, a2, off);
        merge3(a0, a1, a2, b0, b1, b2);
    }
    if (lane == 0) {
        g_j1[b * M48 + c] = (a0 == JINV) ? COLINV : a0;
        g_j2[b * M48 + c] = a1;
        g_j3[b * M48 + c] = a2;
    }
}

// ---------------- top-3 via column factorization, warp-per-m ----------------
__device__ __forceinline__ void ins3(float v, int j,
                                     float& v0, int& i0, float& v1, int& i1, float& v2, int& i2) {
    bool b2 = (v > v2) || (v == v2 && j < i2);
    if (b2) {
        bool b1 = (v > v1) || (v == v1 && j < i1);
        if (b1) {
            bool b0 = (v > v0) || (v == v0 && j < i0);
            if (b0) { v2 = v1; i2 = i1; v1 = v0; i1 = i0; v0 = v; i0 = j; }
            else    { v2 = v1; i2 = i1; v1 = v;  i1 = j; }
        } else      { v2 = v;  i2 = j; }
    }
}

__device__ __forceinline__ void ins3p(float v, int j, int c,
                                      float& v0, int& i0, int& p0,
                                      float& v1, int& i1, int& p1,
                                      float& v2, int& i2, int& p2) {
    bool b2 = (v > v2) || (v == v2 && j < i2);
    if (b2) {
        bool b1 = (v > v1) || (v == v1 && j < i1);
        if (b1) {
            bool b0 = (v > v0) || (v == v0 && j < i0);
            if (b0) { v2 = v1; i2 = i1; p2 = p1; v1 = v0; i1 = i0; p1 = p0; v0 = v; i0 = j; p0 = c; }
            else    { v2 = v1; i2 = i1; p2 = p1; v1 = v;  i1 = j;  p1 = c; }
        } else      { v2 = v;  i2 = j;  p2 = c; }
    }
}

__global__ void __launch_bounds__(256) topk_kernel(float* __restrict__ outS) {
    int b = blockIdx.y;
    int w = threadIdx.x >> 5, lane = threadIdx.x & 31;
    int m = blockIdx.x * 8 + w;
    const float4* Drow4 = (const float4*)(g_D + ((size_t)b * M48 + m) * M48);
    const int4* J4 = (const int4*)(g_j1 + b * M48);

    float v0 = -1e30f, v1 = -1e30f, v2 = -1e30f;
    int   i0 = 1 << 30, i1 = 1 << 30, i2 = 1 << 30;
#pragma unroll
    for (int it = 0; it < 18; it++) {
        int q = lane + it * 32;
        float4 v = __ldg(&Drow4[q]);
        int4 jj = __ldg(&J4[q]);
        int c = q * 4;
        float vx;
        vx = (jj.x == COLINV) ? -1e30f : v.x; ins3(vx, (jj.x << 12) | (c + 0), v0, i0, v1, i1, v2, i2);
        vx = (jj.y == COLINV) ? -1e30f : v.y; ins3(vx, (jj.y << 12) | (c + 1), v0, i0, v1, i1, v2, i2);
        vx = (jj.z == COLINV) ? -1e30f : v.z; ins3(vx, (jj.z << 12) | (c + 2), v0, i0, v1, i1, v2, i2);
        vx = (jj.w == COLINV) ? -1e30f : v.w; ins3(vx, (jj.w << 12) | (c + 3), v0, i0, v1, i1, v2, i2);
    }
#pragma unroll
    for (int off = 16; off; off >>= 1) {
        float w0 = __shfl_down_sync(0xffffffffu, v0, off);
        float w1 = __shfl_down_sync(0xffffffffu, v1, off);
        float w2 = __shfl_down_sync(0xffffffffu, v2, off);
        int   a0 = __shfl_down_sync(0xffffffffu, i0, off);
        int   a1 = __shfl_down_sync(0xffffffffu, i1, off);
        int   a2 = __shfl_down_sync(0xffffffffu, i2, off);
        ins3(w0, a0, v0, i0, v1, i1, v2, i2);
        ins3(w1, a1, v0, i0, v1, i1, v2, i2);
        ins3(w2, a2, v0, i0, v1, i1, v2, i2);
    }
    if (lane == 0) {
        float rv[3] = {v0, v1, v2};
        int   ri[3] = {i0, i1, i2};
        float f0 = -1e30f, f1 = -1e30f, f2 = -1e30f;
        int   a0 = 1 << 30, a1 = 1 << 30, a2 = 1 << 30;
        int   p0 = 0, p1 = 0, p2 = 0;
#pragma unroll
        for (int k = 0; k < 3; k++) {
            int idx = ri[k];
            int jA = idx >> 12;
            int c  = idx & 0xFFF;
            if (jA >= COLINV || rv[k] <= -1e30f) continue;
            float val = rv[k];
            ins3p(val, jA, c, f0, a0, p0, f1, a1, p1, f2, a2, p2);
            int jB = g_j2[b * M48 + c];
            if (jB < JINV) ins3p(val, jB, c, f0, a0, p0, f1, a1, p1, f2, a2, p2);
            int jC = g_j3[b * M48 + c];
            if (jC < JINV) ins3p(val, jC, c, f0, a0, p0, f1, a1, p1, f2, a2, p2);
        }
        outS[(0 * BATCH + b) * M48 + m] = f0;
        outS[(1 * BATCH + b) * M48 + m] = f1;
        outS[(2 * BATCH + b) * M48 + m] = f2;
        g_src[(0 * BATCH + b) * M48 + m] = p0;
        g_src[(1 * BATCH + b) * M48 + m] = p1;
        g_src[(2 * BATCH + b) * M48 + m] = p2;
    }
}

// ---------------- build per-GROUP packed gather tables ----------------
__device__ __forceinline__ void tbuild_one(int R, int S, int tabOfs, int npl, int p) {
    int xg = p % 48; int rest = p / 48;
    int y = rest % S; int ib = rest / S;
    int x0 = xg * R;
    int b = ib & 1, i = ib >> 1;

    const int* srcTab = g_src + (i * BATCH + b) * M48;
    int yp = y + R, xp = x0 + R;
    int v = yp - 3 * R + 1; int milo = (v <= 0) ? 0 : (v + R - 1) / R;
    int mihi = yp / R; if (mihi > 47) mihi = 47;
    v = xp - 3 * R + 1; int mjlo = (v <= 0) ? 0 : (v + R - 1) / R;
    int mjhi = xp / R; if (mjhi > 47) mjhi = 47;

#pragma unroll
    for (int a = 0; a < 3; a++) {
        int mi = milo + a;
#pragma unroll
        for (int e = 0; e < 3; e++) {
            int mj = mjlo + e;
            int u = a * 3 + e;
            int off = -1;
            if (mi <= mihi && mj <= mjhi) {
                int s = srcTab[mi * HW + mj];
                int smi = s / HW, smj = s % HW;
                int ry = y + (smi - mi) * R;
                int rx = x0 + (smj - mj) * R;
                if (ry >= 0 && ry < S && rx >= 0 && rx < S) off = ry * S + rx;
            }
            g_toff[tabOfs + u * npl + p] = off;
        }
    }
}

__global__ void tbuild_all_kernel() {
    int t = blockIdx.x * blockDim.x + threadIdx.x;
    if (t < NPL3)               tbuild_one(1, 48,  TOFS3, NPL3, t);
    else if (t < NPL3 + NPL2)   tbuild_one(2, 96,  TOFS2, NPL2, t - NPL3);
    else if (t < NTB)           tbuild_one(4, 192, TOFS1, NPL1, t - NPL3 - NPL2);
}

// ---------------- transfer lv2 + lv1 (plane-major, group-vectorized) ----------------
template <int G>
__device__ __forceinline__ void transfer_one(const float* __restrict__ ref,
                                             float* __restrict__ out,
                                             int C, int S, int tabOfs, int t) {
    int xg = t % 48; int rest = t / 48;
    int y = rest % S; rest /= S;
    int nCh = C / 16;
    int cc = rest % nCh; int ib = rest / nCh;
    int npl = 6 * S * 48;
    int p = (ib * S + y) * 48 + xg;

    int off[9];
#pragma unroll
    for (int u = 0; u < 9; u++) off[u] = g_toff[tabOfs + u * npl + p];

    int b = ib & 1, i = ib >> 1;
    int ss = S * S;
    const float* refb = ref + ((size_t)(b * C + cc * 16)) * ss;
    float* outb = out + ((size_t)(i * BATCH + b) * C + cc * 16) * ss + y * S + xg * G;
#pragma unroll
    for (int c = 0; c < 16; c++) {
        const float* rc = refb + (size_t)c * ss;
        if (G == 4) {
            float a0 = 0.f, a1 = 0.f, a2 = 0.f, a3 = 0.f;
#pragma unroll
            for (int u = 0; u < 9; u++) {
                int o = off[u];
                if (o >= 0) {
                    float4 vv = __ldg((const float4*)(rc + o));
                    a0 += vv.x; a1 += vv.y; a2 += vv.z; a3 += vv.w;
                }
            }
            float4 o4;
            o4.x = a0 * (1.0f / 9.0f); o4.y = a1 * (1.0f / 9.0f);
            o4.z = a2 * (1.0f / 9.0f); o4.w = a3 * (1.0f / 9.0f);
            *(float4*)(outb + (size_t)c * ss) = o4;
        } else {
            float a0 = 0.f, a1 = 0.f;
#pragma unroll
            for (int u = 0; u < 9; u++) {
                int o = off[u];
                if (o >= 0) {
                    float2 vv = __ldg((const float2*)(rc + o));
                    a0 += vv.x; a1 += vv.y;
                }
            }
            float2 o2;
            o2.x = a0 * (1.0f / 9.0f); o2.y = a1 * (1.0f / 9.0f);
            *(float2*)(outb + (size_t)c * ss) = o2;
        }
    }
}

__global__ void transfer_l21_kernel(const float* __restrict__ ref2, float* __restrict__ out2,
                                    const float* __restrict__ ref1, float* __restrict__ out1) {
    int t = blockIdx.x * blockDim.x + threadIdx.x;
    if (t < NTG2) transfer_one<2>(ref2, out2, 128, 96,  TOFS2, t);
    else          transfer_one<4>(ref1, out1, 64,  192, TOFS1, t - NTG2);
}

// ---------------- lv3 gather: channel-last, warp per (ib, pixel) ----------------
__global__ void __launch_bounds__(256) gather3_kernel() {
    int warp = (blockIdx.x * 256 + threadIdx.x) >> 5;   // 0..13823
    int lane = threadIdx.x & 31;
    int px = warp % M48;
    int ib = warp / M48;
    int b = ib & 1;
    int p = ib * M48 + px;

    int o = -1;
    if (lane < 9) o = g_toff[TOFS3 + lane * NPL3 + p];
    int off[9];
#pragma unroll
    for (int u = 0; u < 9; u++) off[u] = __shfl_sync(0xffffffffu, o, u);

    const float* src = g_r3T + (size_t)b * M48 * C3;
    float* dst = g_o3T + ((size_t)ib * M48 + px) * C3;
#pragma unroll
    for (int ch = 0; ch < 8; ch++) {
        int c = ch * 32 + lane;
        float acc = 0.f;
#pragma unroll
        for (int u = 0; u < 9; u++) {
            int oo = off[u];
            if (oo >= 0) acc += __ldg(src + (size_t)oo * C3 + c);
        }
        dst[c] = acc * (1.0f / 9.0f);
    }
}

// ---------------- transpose lv3 output back to plane-major ----------------
__global__ void t_out3_kernel(float* __restrict__ out3) {
    __shared__ float tile[32][33];
    int x0 = blockIdx.x * 32, c0 = blockIdx.y * 32, ib = blockIdx.z;
    int tx = threadIdx.x, ty = threadIdx.y;   // 32 x 8
#pragma unroll
    for (int r = 0; r < 32; r += 8)
        tile[ty + r][tx] = g_o3T[((size_t)ib * M48 + x0 + ty + r) * C3 + c0 + tx];
    __syncthreads();
#pragma unroll
    for (int r = 0; r < 32; r += 8)
        out3[((size_t)(ib * C3 + c0 + ty + r)) * M48 + x0 + tx] = tile[tx][ty + r];
}

// ---------------- launch ----------------
extern "C" void kernel_launch(void* const* d_in, const int* in_sizes, int n_in,
                              void* d_out, int out_size) {
    const float* lr    = (const float*)d_in[0];
    const float* refsr = (const float*)d_in[1];
    const float* ref1  = (const float*)d_in[2];
    const float* ref2  = (const float*)d_in[3];
    const float* ref3  = (const float*)d_in[4];
    float* out = (float*)d_out;

    float* outS  = out;
    float* outT3 = outS + 3 * BATCH * M48;
    float* outT2 = outT3 + 3 * BATCH * C3 * M48;
    float* outT1 = outT2 + 3 * BATCH * 128 * 96 * 96;

    prep_ssq_kernel<<<(NPREP + 255) / 256, 256>>>(lr, refsr);              // 1
    t_in3_kernel<<<dim3(72, 8, BATCH), dim3(32, 8)>>>(ref3);               // 2

    cudaFuncSetAttribute(gemm_kernel, cudaFuncAttributeMaxDynamicSharedMemorySize, GEMM_SMEM);
    gemm_kernel<<<dim3(20, 20, BATCH), 256, GEMM_SMEM>>>();                // 3

    agg_tile_kernel<<<dim3(48, 48, BATCH), 256>>>();                       // 4 (profiled slot)
    colidx_kernel<<<dim3(M48 / 8, BATCH), 256>>>();                        // 5
    topk_kernel<<<dim3(M48 / 8, BATCH), 256>>>(outS);                      // 6

    tbuild_all_kernel<<<(NTB + 255) / 256, 256>>>();                       // 7
    transfer_l21_kernel<<<(NTG2 + NTG1) / 256, 256>>>(ref2, outT2, ref1, outT1);  // 8
    gather3_kernel<<<(6 * M48 * 32) / 256, 256>>>();                       // 9
    t_out3_kernel<<<dim3(72, 8, 6), dim3(32, 8)>>>(outT3);                 // 10
}

// round 17
// speedup vs baseline: 1.1848x; 1.0188x over previous
#include <cuda_runtime.h>
#include <cstdint>

// ---------------- problem constants ----------------
#define BATCH 2
#define C3 256
#define HW 48
#define M48 (HW*HW)     // 2304
#define HP 50
#define NP 2500
#define NPS 2560
#define KTILE 32
#define NKSTEPS 8
#define STAGES 3
#define GEMM_SMEM (STAGES * KTILE * 128 * 2 * 4)
#define COLINV 4095
#define JINV (1 << 30)

#define NPL3 (6 * 48 * 48)
#define NPL2 (6 * 96 * 48)
#define NPL1 (6 * 192 * 48)
#define TOFS3 0
#define TOFS2 (9 * NPL3)
#define TOFS1 (TOFS2 + 9 * NPL2)
#define TTOT  (TOFS1 + 9 * NPL1)
#define NTB   (NPL3 + NPL2 + NPL1)

#define NTG1 (6 * 4 * 192 * 48)    // 221184 threads for lv1 plane-major transfer

#define PX2 (96 * 96)              // 9216
#define NSSQ (2 * BATCH * NP)
#define NPREP (2 * BATCH * C3 * NPS)

// t_in tiles: lv3 72x8x2 = 1152 ; lv2 288x4x2 = 2304
#define TIN3 1152
#define TIN_TOT (TIN3 + 2304)
// t_out tiles: lv3 72x8x6 = 3456 ; lv2 288x4x6 = 6912
#define TOUT3 3456
#define TOUT_TOT (TOUT3 + 6912)
// gather warps: lv3 6*2304 ; lv2 6*9216
#define GW3 (6 * M48)
#define GW_TOT (GW3 + 6 * PX2)

// ---------------- scratch ----------------
__device__ __align__(16) float g_lrp[BATCH * C3 * NPS];
__device__ __align__(16) float g_rfp[BATCH * C3 * NPS];
__device__ __align__(16) float g_E[(size_t)BATCH * NPS * NPS];
__device__ __align__(16) float g_D[(size_t)BATCH * M48 * M48];
__device__ float g_SS[2 * BATCH * NP];
__device__ unsigned long long g_H64[BATCH * M48];
__device__ int   g_src[3 * BATCH * M48];
__device__ int   g_toff[TTOT];
__device__ __align__(16) int g_j1[BATCH * M48];
__device__ int   g_j2[BATCH * M48];
__device__ int   g_j3[BATCH * M48];
__device__ __align__(16) float g_r3T[BATCH * M48 * C3];      // ref3 channel-last
__device__ __align__(16) float g_o3T[6 * M48 * C3];          // lv3 out channel-last
__device__ __align__(16) float g_r2T[BATCH * PX2 * 128];     // ref2 channel-last (9.4 MB)
__device__ __align__(16) float g_o2T[(size_t)6 * PX2 * 128]; // lv2 out channel-last (28.3 MB)

// ---------------- fused prep + ssq + H64 init ----------------
__global__ void prep_ssq_kernel(const float* __restrict__ lr, const float* __restrict__ refsr) {
    int t = blockIdx.x * blockDim.x + threadIdx.x;
    if (t < BATCH * M48) g_H64[t] = 0ull;
    if (t < NPREP) {
        int u = t % NPS; int r = t / NPS;
        int c = r % C3; r /= C3;
        int b = r & 1; int which = r >> 1;
        float val = 0.f;
        if (u < NP) {
            int rr = u / HP, cc = u % HP;
            if (rr >= 1 && rr < 49 && cc >= 1 && cc < 49) {
                const float* src = which ? refsr : lr;
                val = src[((size_t)(b * C3 + c)) * M48 + (rr - 1) * HW + (cc - 1)];
            }
        }
        float* dst = which ? g_rfp : g_lrp;
        dst[((size_t)(b * C3 + c)) * NPS + u] = val;
    }
    if (t < NSSQ) {
        int u = t % NP; int b = (t / NP) & 1; int which = t / (BATCH * NP);
        int rr = u / HP, cc = u % HP;
        float acc = 0.f;
        if (rr >= 1 && rr < 49 && cc >= 1 && cc < 49) {
            const float* src = (which ? refsr : lr) + (size_t)b * C3 * M48 + (rr - 1) * HW + (cc - 1);
#pragma unroll 8
            for (int c = 0; c < C3; c++) { float x = src[(size_t)c * M48]; acc += x * x; }
        }
        g_SS[t] = acc;
    }
}

// ---------------- transpose ref3 + ref2 -> channel-last ----------------
__global__ void t_in_kernel(const float* __restrict__ ref3, const float* __restrict__ ref2) {
    __shared__ float tile[32][33];
    int bi = blockIdx.x;
    const float* src; float* dst; int x0, c0, b, C, NPX;
    if (bi < TIN3) {
        int xt = bi % 72; int r = bi / 72; int ct = r % 8; b = r / 8;
        src = ref3; dst = g_r3T; C = 256; NPX = M48; x0 = xt * 32; c0 = ct * 32;
    } else {
        bi -= TIN3;
        int xt = bi % 288; int r = bi / 288; int ct = r % 4; b = r / 4;
        src = ref2; dst = g_r2T; C = 128; NPX = PX2; x0 = xt * 32; c0 = ct * 32;
    }
    int tx = threadIdx.x, ty = threadIdx.y;   // 32 x 8
#pragma unroll
    for (int r = 0; r < 32; r += 8)
        tile[ty + r][tx] = src[((size_t)(b * C + c0 + ty + r)) * NPX + x0 + tx];
    __syncthreads();
#pragma unroll
    for (int r = 0; r < 32; r += 8)
        dst[((size_t)b * NPX + x0 + ty + r) * C + c0 + tx] = tile[tx][ty + r];
}

// ---------------- SGEMM (FFMA2, cp.async, KTILE=32) ----------------
__device__ __forceinline__ void issue_tile(float* as, float* bs,
                                           const float* Aptr, const float* Bptr,
                                           int kt, int lk, int lc) {
#pragma unroll
    for (int r = 0; r < 4; r++) {
        uint32_t sa = (uint32_t)__cvta_generic_to_shared(as + (lk + 8 * r) * 128 + lc);
        const float* ga = Aptr + ((size_t)kt * KTILE + 8 * r) * NPS;
        asm volatile("cp.async.ca.shared.global [%0], [%1], 16;\n" :: "r"(sa), "l"(ga));
    }
#pragma unroll
    for (int r = 0; r < 4; r++) {
        uint32_t sb = (uint32_t)__cvta_generic_to_shared(bs + (lk + 8 * r) * 128 + lc);
        const float* gb = Bptr + ((size_t)kt * KTILE + 8 * r) * NPS;
        asm volatile("cp.async.ca.shared.global [%0], [%1], 16;\n" :: "r"(sb), "l"(gb));
    }
    asm volatile("cp.async.commit_group;\n" ::: "memory");
}

__global__ void __launch_bounds__(256) gemm_kernel() {
    int b = blockIdx.z;
    const float* A = g_lrp + (size_t)b * C3 * NPS;
    const float* B = g_rfp + (size_t)b * C3 * NPS;
    float* C = g_E + (size_t)b * NPS * NPS;

    extern __shared__ __align__(16) float smemf[];
    float* smA = smemf;
    float* smB = smemf + STAGES * KTILE * 128;

    int tid = threadIdx.x;
    int iBase = blockIdx.x * 128;
    int jBase = blockIdx.y * 128;
    int lk = tid >> 5;
    int lc = (tid & 31) << 2;
    const float* Aptr = A + (size_t)lk * NPS + iBase + lc;
    const float* Bptr = B + (size_t)lk * NPS + jBase + lc;

    issue_tile(smA + 0 * KTILE * 128, smB + 0 * KTILE * 128, Aptr, Bptr, 0, lk, lc);
    issue_tile(smA + 1 * KTILE * 128, smB + 1 * KTILE * 128, Aptr, Bptr, 1, lk, lc);

    int ty = tid >> 4, tx = tid & 15;

    unsigned long long accp[8][4];
#pragma unroll
    for (int i = 0; i < 8; i++)
#pragma unroll
        for (int j = 0; j < 4; j++) accp[i][j] = 0ull;

    for (int kt = 0; kt < NKSTEPS; kt++) {
        asm volatile("cp.async.wait_group 1;\n" ::: "memory");
        __syncthreads();
        if (kt + 2 < NKSTEPS) {
            int st = (kt + 2) % STAGES;
            issue_tile(smA + st * KTILE * 128, smB + st * KTILE * 128, Aptr, Bptr, kt + 2, lk, lc);
        }
        int cur = kt % STAGES;
        const float* As = smA + cur * KTILE * 128;
        const float* Bs = smB + cur * KTILE * 128;
#pragma unroll
        for (int kk = 0; kk < KTILE; kk++) {
            float4 a0 = *(const float4*)&As[kk * 128 + ty * 4];
            float4 a1 = *(const float4*)&As[kk * 128 + 64 + ty * 4];
            unsigned long long bp[4];
            *(ulonglong2*)(bp)     = *(const ulonglong2*)&Bs[kk * 128 + tx * 4];
            *(ulonglong2*)(bp + 2) = *(const ulonglong2*)&Bs[kk * 128 + 64 + tx * 4];
            float ar[8] = {a0.x, a0.y, a0.z, a0.w, a1.x, a1.y, a1.z, a1.w};
#pragma unroll
            for (int i = 0; i < 8; i++) {
                unsigned long long a2;
                asm("mov.b64 %0, {%1, %1};" : "=l"(a2) : "r"(__float_as_uint(ar[i])));
#pragma unroll
                for (int jp = 0; jp < 4; jp++) {
                    asm("fma.rn.f32x2 %0, %1, %2, %0;"
                        : "+l"(accp[i][jp]) : "l"(a2), "l"(bp[jp]));
                }
            }
        }
    }

#pragma unroll
    for (int half = 0; half < 2; half++) {
#pragma unroll
        for (int ii = 0; ii < 4; ii++) {
            int i = half * 4 + ii;
            int row = iBase + half * 64 + ty * 4 + ii;
            float* crow = C + (size_t)row * NPS + jBase;
            *(ulonglong2*)(crow + tx * 4)      = make_ulonglong2(accp[i][0], accp[i][1]);
            *(ulonglong2*)(crow + 64 + tx * 4) = make_ulonglong2(accp[i][2], accp[i][3]);
        }
    }
}

// ---------------- tiled aggregate (di-fold) + inline norms + packed atomic argmax -------
__global__ void __launch_bounds__(256) agg_tile_kernel() {
    int li = blockIdx.x, mi = blockIdx.y, b = blockIdx.z;
    __shared__ __align__(16) float Ps[50 * 56];
    __shared__ __align__(16) float dt[48 * 48];
    __shared__ float invqs[48], invks[48];

    const float* Eb = g_E + (size_t)b * NPS * NPS;
    int tid = threadIdx.x;

    if (tid < 48) {
        const float* S = g_SS + (0 * BATCH + b) * NP;
        float s = 0.f;
#pragma unroll
        for (int di = 0; di < 3; di++)
#pragma unroll
            for (int dj = 0; dj < 3; dj++)
                s += S[(mi + di) * HP + tid + dj];
        invqs[tid] = 1.0f / fmaxf(sqrtf(s), 1e-12f);
    } else if (tid >= 64 && tid < 112) {
        int j = tid - 64;
        const float* S = g_SS + (1 * BATCH + b) * NP;
        float s = 0.f;
#pragma unroll
        for (int di = 0; di < 3; di++)
#pragma unroll
            for (int dj = 0; dj < 3; dj++)
                s += S[(li + di) * HP + j + dj];
        invks[j] = 1.0f / fmaxf(sqrtf(s), 1e-12f);
    }

    for (int idx = tid; idx < 1250; idx += 256) {
        int a = idx / 25, c2 = idx - (idx / 25) * 25;
        const float* e0 = Eb + (size_t)((mi + 0) * HP + a) * NPS + (li + 0) * HP + c2 * 2;
        const float* e1 = Eb + (size_t)((mi + 1) * HP + a) * NPS + (li + 1) * HP + c2 * 2;
        const float* e2 = Eb + (size_t)((mi + 2) * HP + a) * NPS + (li + 2) * HP + c2 * 2;
        float2 v0 = *(const float2*)e0;
        float2 v1 = *(const float2*)e1;
        float2 v2 = *(const float2*)e2;
        float2 p;
        p.x = v0.x + v1.x + v2.x;
        p.y = v0.y + v1.y + v2.y;
        *(float2*)&Ps[a * 56 + c2 * 2] = p;
    }
    __syncthreads();

    for (int g = tid; g < 576; g += 256) {
        int mj = g / 12, lj0 = (g - (g / 12) * 12) * 4;
        const float* r0 = &Ps[(mj + 0) * 56 + lj0];
        const float* r1 = &Ps[(mj + 1) * 56 + lj0];
        const float* r2 = &Ps[(mj + 2) * 56 + lj0];
        float4 x0 = *(const float4*)r0;
        float4 x1 = *(const float4*)r1;  float4 y1 = *(const float4*)(r1 + 4);
        float4 x2 = *(const float4*)r2;  float4 y2 = *(const float4*)(r2 + 4);
        float s0 = x0.x + x1.y + x2.z;
        float s1 = x0.y + x1.z + x2.w;
        float s2 = x0.z + x1.w + y2.x;
        float s3 = x0.w + y1.x + y2.y;
        int m = mi * 48 + mj;
        int l0 = li * 48 + lj0;
        float qi = invqs[mj];
        float4 o;
        o.x = s0 * qi * invks[lj0];
        o.y = s1 * qi * invks[lj0 + 1];
        o.z = s2 * qi * invks[lj0 + 2];
        o.w = s3 * qi * invks[lj0 + 3];
        *(float4*)&g_D[((size_t)b * M48 + m) * M48 + l0] = o;
        *(float4*)&dt[mj * 48 + lj0] = o;
    }
    __syncthreads();

    int w = tid >> 5, lane = tid & 31;
#pragma unroll
    for (int r = 0; r < 6; r++) {
        int mj = w * 6 + r;
        float v = dt[mj * 48 + lane]; int idx = lane;
        if (lane < 16) {
            float v2 = dt[mj * 48 + 32 + lane];
            if (v2 > v) { v = v2; idx = 32 + lane; }
        }
#pragma unroll
        for (int off = 16; off; off >>= 1) {
            float v2 = __shfl_down_sync(0xffffffffu, v, off);
            int i2 = __shfl_down_sync(0xffffffffu, idx, off);
            if (v2 > v || (v2 == v && i2 < idx)) { v = v2; idx = i2; }
        }
        if (lane == 0) {
            int m = mi * 48 + mj;
            int l = li * 48 + idx;
            unsigned int ub = __float_as_uint(v);
            unsigned int mono = (ub & 0x80000000u) ? ~ub : (ub | 0x80000000u);
            unsigned long long key = ((unsigned long long)mono << 32) | (0xFFFFFFFFu - (unsigned)l);
            atomicMax(&g_H64[b * M48 + m], key);
        }
    }
}

// ---------------- colidx: warp-per-column 3-smallest j with hs[j]=c ----------------
__device__ __forceinline__ void merge3(int& a0, int& a1, int& a2, int b0, int b1, int b2) {
    int m0 = min(a0, b0), M0 = max(a0, b0);
    int m1 = min(a1, b1), M1 = max(a1, b1);
    int m2 = min(a2, b2);
    int r1 = min(M0, m1);
    int r2 = min(max(M0, m1), min(M1, m2));
    a0 = m0; a1 = r1; a2 = r2;
}

__global__ void __launch_bounds__(256) colidx_kernel() {
    int b = blockIdx.y;
    int tid = threadIdx.x;
    int w = tid >> 5, lane = tid & 31;
    int c = blockIdx.x * 8 + w;
    __shared__ int hsx[M48];
    const unsigned long long* Hb = g_H64 + b * M48;
#pragma unroll
    for (int it = 0; it < 9; it++) {
        int j = tid + it * 256;
        hsx[j] = (int)(0xFFFFFFFFu - (unsigned)Hb[j]);
    }
    __syncthreads();

    int a0 = JINV, a1 = JINV, a2 = JINV;
    for (int j = lane; j < M48; j += 32) {
        if (hsx[j] == c) {
            if (a0 == JINV) a0 = j;
            else if (a1 == JINV) a1 = j;
            else if (a2 == JINV) a2 = j;
        }
    }
#pragma unroll
    for (int off = 16; off; off >>= 1) {
        int b0 = __shfl_down_sync(0xffffffffu, a0, off);
        int b1 = __shfl_down_sync(0xffffffffu, a1, off);
        int b2 = __shfl_down_sync(0xffffffffu, a2, off);
        merge3(a0, a1, a2, b0, b1, b2);
    }
    if (lane == 0) {
        g_j1[b * M48 + c] = (a0 == JINV) ? COLINV : a0;
        g_j2[b * M48 + c] = a1;
        g_j3[b * M48 + c] = a2;
    }
}

// ---------------- top-3 via column factorization, warp-per-m ----------------
__device__ __forceinline__ void ins3(float v, int j,
                                     float& v0, int& i0, float& v1, int& i1, float& v2, int& i2) {
    bool b2 = (v > v2) || (v == v2 && j < i2);
    if (b2) {
        bool b1 = (v > v1) || (v == v1 && j < i1);
        if (b1) {
            bool b0 = (v > v0) || (v == v0 && j < i0);
            if (b0) { v2 = v1; i2 = i1; v1 = v0; i1 = i0; v0 = v; i0 = j; }
            else    { v2 = v1; i2 = i1; v1 = v;  i1 = j; }
        } else      { v2 = v;  i2 = j; }
    }
}

__device__ __forceinline__ void ins3p(float v, int j, int c,
                                      float& v0, int& i0, int& p0,
                                      float& v1, int& i1, int& p1,
                                      float& v2, int& i2, int& p2) {
    bool b2 = (v > v2) || (v == v2 && j < i2);
    if (b2) {
        bool b1 = (v > v1) || (v == v1 && j < i1);
        if (b1) {
            bool b0 = (v > v0) || (v == v0 && j < i0);
            if (b0) { v2 = v1; i2 = i1; p2 = p1; v1 = v0; i1 = i0; p1 = p0; v0 = v; i0 = j; p0 = c; }
            else    { v2 = v1; i2 = i1; p2 = p1; v1 = v;  i1 = j;  p1 = c; }
        } else      { v2 = v;  i2 = j;  p2 = c; }
    }
}

__global__ void __launch_bounds__(256) topk_kernel(float* __restrict__ outS) {
    int b = blockIdx.y;
    int w = threadIdx.x >> 5, lane = threadIdx.x & 31;
    int m = blockIdx.x * 8 + w;
    const float4* Drow4 = (const float4*)(g_D + ((size_t)b * M48 + m) * M48);
    const int4* J4 = (const int4*)(g_j1 + b * M48);

    float v0 = -1e30f, v1 = -1e30f, v2 = -1e30f;
    int   i0 = 1 << 30, i1 = 1 << 30, i2 = 1 << 30;
#pragma unroll
    for (int it = 0; it < 18; it++) {
        int q = lane + it * 32;
        float4 v = __ldg(&Drow4[q]);
        int4 jj = __ldg(&J4[q]);
        int c = q * 4;
        float vx;
        vx = (jj.x == COLINV) ? -1e30f : v.x; ins3(vx, (jj.x << 12) | (c + 0), v0, i0, v1, i1, v2, i2);
        vx = (jj.y == COLINV) ? -1e30f : v.y; ins3(vx, (jj.y << 12) | (c + 1), v0, i0, v1, i1, v2, i2);
        vx = (jj.z == COLINV) ? -1e30f : v.z; ins3(vx, (jj.z << 12) | (c + 2), v0, i0, v1, i1, v2, i2);
        vx = (jj.w == COLINV) ? -1e30f : v.w; ins3(vx, (jj.w << 12) | (c + 3), v0, i0, v1, i1, v2, i2);
    }
#pragma unroll
    for (int off = 16; off; off >>= 1) {
        float w0 = __shfl_down_sync(0xffffffffu, v0, off);
        float w1 = __shfl_down_sync(0xffffffffu, v1, off);
        float w2 = __shfl_down_sync(0xffffffffu, v2, off);
        int   a0 = __shfl_down_sync(0xffffffffu, i0, off);
        int   a1 = __shfl_down_sync(0xffffffffu, i1, off);
        int   a2 = __shfl_down_sync(0xffffffffu, i2, off);
        ins3(w0, a0, v0, i0, v1, i1, v2, i2);
        ins3(w1, a1, v0, i0, v1, i1, v2, i2);
        ins3(w2, a2, v0, i0, v1, i1, v2, i2);
    }
    if (lane == 0) {
        float rv[3] = {v0, v1, v2};
        int   ri[3] = {i0, i1, i2};
        float f0 = -1e30f, f1 = -1e30f, f2 = -1e30f;
        int   a0 = 1 << 30, a1 = 1 << 30, a2 = 1 << 30;
        int   p0 = 0, p1 = 0, p2 = 0;
#pragma unroll
        for (int k = 0; k < 3; k++) {
            int idx = ri[k];
            int jA = idx >> 12;
            int c  = idx & 0xFFF;
            if (jA >= COLINV || rv[k] <= -1e30f) continue;
            float val = rv[k];
            ins3p(val, jA, c, f0, a0, p0, f1, a1, p1, f2, a2, p2);
            int jB = g_j2[b * M48 + c];
            if (jB < JINV) ins3p(val, jB, c, f0, a0, p0, f1, a1, p1, f2, a2, p2);
            int jC = g_j3[b * M48 + c];
            if (jC < JINV) ins3p(val, jC, c, f0, a0, p0, f1, a1, p1, f2, a2, p2);
        }
        outS[(0 * BATCH + b) * M48 + m] = f0;
        outS[(1 * BATCH + b) * M48 + m] = f1;
        outS[(2 * BATCH + b) * M48 + m] = f2;
        g_src[(0 * BATCH + b) * M48 + m] = p0;
        g_src[(1 * BATCH + b) * M48 + m] = p1;
        g_src[(2 * BATCH + b) * M48 + m] = p2;
    }
}

// ---------------- build per-GROUP packed gather tables ----------------
__device__ __forceinline__ void tbuild_one(int R, int S, int tabOfs, int npl, int p) {
    int xg = p % 48; int rest = p / 48;
    int y = rest % S; int ib = rest / S;
    int x0 = xg * R;
    int b = ib & 1, i = ib >> 1;

    const int* srcTab = g_src + (i * BATCH + b) * M48;
    int yp = y + R, xp = x0 + R;
    int v = yp - 3 * R + 1; int milo = (v <= 0) ? 0 : (v + R - 1) / R;
    int mihi = yp / R; if (mihi > 47) mihi = 47;
    v = xp - 3 * R + 1; int mjlo = (v <= 0) ? 0 : (v + R - 1) / R;
    int mjhi = xp / R; if (mjhi > 47) mjhi = 47;

#pragma unroll
    for (int a = 0; a < 3; a++) {
        int mi = milo + a;
#pragma unroll
        for (int e = 0; e < 3; e++) {
            int mj = mjlo + e;
            int u = a * 3 + e;
            int off = -1;
            if (mi <= mihi && mj <= mjhi) {
                int s = srcTab[mi * HW + mj];
                int smi = s / HW, smj = s % HW;
                int ry = y + (smi - mi) * R;
                int rx = x0 + (smj - mj) * R;
                if (ry >= 0 && ry < S && rx >= 0 && rx < S) off = ry * S + rx;
            }
            g_toff[tabOfs + u * npl + p] = off;
        }
    }
}

__global__ void tbuild_all_kernel() {
    int t = blockIdx.x * blockDim.x + threadIdx.x;
    if (t < NPL3)               tbuild_one(1, 48,  TOFS3, NPL3, t);
    else if (t < NPL3 + NPL2)   tbuild_one(2, 96,  TOFS2, NPL2, t - NPL3);
    else if (t < NTB)           tbuild_one(4, 192, TOFS1, NPL1, t - NPL3 - NPL2);
}

// ---------------- transfer lv1 (plane-major, group-vectorized float4) ----------------
__global__ void transfer_l1_kernel(const float* __restrict__ ref1, float* __restrict__ out1) {
    int t = blockIdx.x * blockDim.x + threadIdx.x;
    if (t >= NTG1) return;
    int xg = t % 48; int rest = t / 48;
    int y = rest % 192; rest /= 192;
    int cc = rest % 4; int ib = rest / 4;
    int npl = NPL1;
    int p = (ib * 192 + y) * 48 + xg;

    int off[9];
#pragma unroll
    for (int u = 0; u < 9; u++) off[u] = g_toff[TOFS1 + u * npl + p];

    int b = ib & 1, i = ib >> 1;
    int ss = 192 * 192;
    const float* refb = ref1 + ((size_t)(b * 64 + cc * 16)) * ss;
    float* outb = out1 + ((size_t)(i * BATCH + b) * 64 + cc * 16) * ss + y * 192 + xg * 4;
#pragma unroll
    for (int c = 0; c < 16; c++) {
        const float* rc = refb + (size_t)c * ss;
        float a0 = 0.f, a1 = 0.f, a2 = 0.f, a3 = 0.f;
#pragma unroll
        for (int u = 0; u < 9; u++) {
            int o = off[u];
            if (o >= 0) {
                float4 vv = __ldg((const float4*)(rc + o));
                a0 += vv.x; a1 += vv.y; a2 += vv.z; a3 += vv.w;
            }
        }
        float4 o4;
        o4.x = a0 * (1.0f / 9.0f); o4.y = a1 * (1.0f / 9.0f);
        o4.z = a2 * (1.0f / 9.0f); o4.w = a3 * (1.0f / 9.0f);
        *(float4*)(outb + (size_t)c * ss) = o4;
    }
}

// ---------------- gather lv3 + lv2: channel-last, warp per (ib, pixel) ----------------
__global__ void __launch_bounds__(256) gather23_kernel() {
    int warp = (blockIdx.x * 256 + threadIdx.x) >> 5;
    int lane = threadIdx.x & 31;
    if (warp < GW3) {
        int px = warp % M48;
        int ib = warp / M48;
        int b = ib & 1;
        int p = ib * M48 + px;
        int o = (lane < 9) ? g_toff[TOFS3 + lane * NPL3 + p] : -1;
        int off[9];
#pragma unroll
        for (int u = 0; u < 9; u++) off[u] = __shfl_sync(0xffffffffu, o, u);
        const float* src = g_r3T + (size_t)b * M48 * C3;
        float* dst = g_o3T + ((size_t)ib * M48 + px) * C3;
#pragma unroll
        for (int ch = 0; ch < 8; ch++) {
            int c = ch * 32 + lane;
            float acc = 0.f;
#pragma unroll
            for (int u = 0; u < 9; u++) {
                int oo = off[u];
                if (oo >= 0) acc += __ldg(src + (size_t)oo * C3 + c);
            }
            dst[c] = acc * (1.0f / 9.0f);
        }
    } else {
        int w2 = warp - GW3;
        int px = w2 % PX2;
        int ib = w2 / PX2;
        int b = ib & 1;
        int y = px / 96, x = px - (px / 96) * 96;
        int p = (ib * 96 + y) * 48 + (x >> 1);
        int d = x & 1;
        int o = (lane < 9) ? g_toff[TOFS2 + lane * NPL2 + p] : -1;
        int off[9];
#pragma unroll
        for (int u = 0; u < 9; u++) {
            int oo = __shfl_sync(0xffffffffu, o, u);
            off[u] = (oo >= 0) ? oo + d : -1;
        }
        const float* src = g_r2T + (size_t)b * PX2 * 128;
        float* dst = g_o2T + ((size_t)ib * PX2 + px) * 128;
#pragma unroll
        for (int ch = 0; ch < 4; ch++) {
            int c = ch * 32 + lane;
            float acc = 0.f;
#pragma unroll
            for (int u = 0; u < 9; u++) {
                int oo = off[u];
                if (oo >= 0) acc += __ldg(src + (size_t)oo * 128 + c);
            }
            dst[c] = acc * (1.0f / 9.0f);
        }
    }
}

// ---------------- transpose lv3 + lv2 outputs back to plane-major ----------------
__global__ void t_out_kernel(float* __restrict__ out3, float* __restrict__ out2) {
    __shared__ float tile[32][33];
    int bi = blockIdx.x;
    const float* src; float* dst; int x0, c0, ib, C, NPX;
    if (bi < TOUT3) {
        int xt = bi % 72; int r = bi / 72; int ct = r % 8; ib = r / 8;
        src = g_o3T; dst = out3; C = 256; NPX = M48; x0 = xt * 32; c0 = ct * 32;
    } else {
        bi -= TOUT3;
        int xt = bi % 288; int r = bi / 288; int ct = r % 4; ib = r / 4;
        src = g_o2T; dst = out2; C = 128; NPX = PX2; x0 = xt * 32; c0 = ct * 32;
    }
    int tx = threadIdx.x, ty = threadIdx.y;   // 32 x 8
#pragma unroll
    for (int r = 0; r < 32; r += 8)
        tile[ty + r][tx] = src[((size_t)ib * NPX + x0 + ty + r) * C + c0 + tx];
    __syncthreads();
#pragma unroll
    for (int r = 0; r < 32; r += 8)
        dst[((size_t)(ib * C + c0 + ty + r)) * NPX + x0 + tx] = tile[tx][ty + r];
}

// ---------------- launch ----------------
extern "C" void kernel_launch(void* const* d_in, const int* in_sizes, int n_in,
                              void* d_out, int out_size) {
    const float* lr    = (const float*)d_in[0];
    const float* refsr = (const float*)d_in[1];
    const float* ref1  = (const float*)d_in[2];
    const float* ref2  = (const float*)d_in[3];
    const float* ref3  = (const float*)d_in[4];
    float* out = (float*)d_out;

    float* outS  = out;
    float* outT3 = outS + 3 * BATCH * M48;
    float* outT2 = outT3 + 3 * BATCH * C3 * M48;
    float* outT1 = outT2 + 3 * BATCH * 128 * 96 * 96;

    prep_ssq_kernel<<<(NPREP + 255) / 256, 256>>>(lr, refsr);              // 1
    t_in_kernel<<<TIN_TOT, dim3(32, 8)>>>(ref3, ref2);                     // 2

    cudaFuncSetAttribute(gemm_kernel, cudaFuncAttributeMaxDynamicSharedMemorySize, GEMM_SMEM);
    gemm_kernel<<<dim3(20, 20, BATCH), 256, GEMM_SMEM>>>();                // 3

    agg_tile_kernel<<<dim3(48, 48, BATCH), 256>>>();                       // 4 (profiled slot)
    colidx_kernel<<<dim3(M48 / 8, BATCH), 256>>>();                        // 5
    topk_kernel<<<dim3(M48 / 8, BATCH), 256>>>(outS);                      // 6

    tbuild_all_kernel<<<(NTB + 255) / 256, 256>>>();                       // 7
    transfer_l1_kernel<<<(NTG1 + 255) / 256, 256>>>(ref1, outT1);          // 8
    gather23_kernel<<<(GW_TOT * 32) / 256, 256>>>();                       // 9
    t_out_kernel<<<TOUT_TOT, dim3(32, 8)>>>(outT3, outT2);                 // 10
}